// round 5
// baseline (speedup 1.0000x reference)
#include <cuda_runtime.h>
#include <math.h>

#define HH 128
#define SS 65
#define SP 68          // padded S (stride), cols 65..67 kept zero
#define NT 512

typedef unsigned long long u64;

// ---------- f32x2 packed helpers (per-lane IEEE fp32, identical rounding) ----------
__device__ __forceinline__ u64 pack2(float lo, float hi) {
    u64 r; asm("mov.b64 %0, {%1, %2};" : "=l"(r) : "f"(lo), "f"(hi)); return r;
}
__device__ __forceinline__ float2 unpack2(u64 p) {
    float2 v; asm("mov.b64 {%0, %1}, %2;" : "=f"(v.x), "=f"(v.y) : "l"(p)); return v;
}
__device__ __forceinline__ u64 fma2(u64 a, u64 b, u64 c) {
    u64 d; asm("fma.rn.f32x2 %0, %1, %2, %3;" : "=l"(d) : "l"(a), "l"(b), "l"(c)); return d;
}

__device__ __forceinline__ float dot4(const float4& a, const float4& b, float acc) {
    acc = fmaf(a.x, b.x, acc);
    acc = fmaf(a.y, b.y, acc);
    acc = fmaf(a.z, b.z, acc);
    acc = fmaf(a.w, b.w, acc);
    return acc;
}

// sC[j*SP + t] = sum_k A[j*HH + k] * sB[k*SP + t]
// Accs packed over (t, t+1); per-element chain = k ascending (bit-identical to scalar).
__device__ __forceinline__ void gemm_A(const float* __restrict__ A,
                                       const float* __restrict__ sB,
                                       float* __restrict__ sC) {
    for (int tile = threadIdx.x; tile < 32 * 17; tile += NT) {
        int j0 = (tile / 17) << 2;
        int t0 = (tile % 17) << 2;
        u64 acc[4][2];
        #pragma unroll
        for (int r = 0; r < 4; r++) { acc[r][0] = 0ull; acc[r][1] = 0ull; }
        #pragma unroll 2
        for (int k = 0; k < HH; k += 4) {
            float4 a0 = *(const float4*)(A + (j0 + 0) * HH + k);
            float4 a1 = *(const float4*)(A + (j0 + 1) * HH + k);
            float4 a2 = *(const float4*)(A + (j0 + 2) * HH + k);
            float4 a3 = *(const float4*)(A + (j0 + 3) * HH + k);
            ulonglong2 b0 = *(const ulonglong2*)(sB + (k + 0) * SP + t0);
            ulonglong2 b1 = *(const ulonglong2*)(sB + (k + 1) * SP + t0);
            ulonglong2 b2 = *(const ulonglong2*)(sB + (k + 2) * SP + t0);
            ulonglong2 b3 = *(const ulonglong2*)(sB + (k + 3) * SP + t0);
            u64 p;
            p = pack2(a0.x, a0.x); acc[0][0] = fma2(p, b0.x, acc[0][0]); acc[0][1] = fma2(p, b0.y, acc[0][1]);
            p = pack2(a0.y, a0.y); acc[0][0] = fma2(p, b1.x, acc[0][0]); acc[0][1] = fma2(p, b1.y, acc[0][1]);
            p = pack2(a0.z, a0.z); acc[0][0] = fma2(p, b2.x, acc[0][0]); acc[0][1] = fma2(p, b2.y, acc[0][1]);
            p = pack2(a0.w, a0.w); acc[0][0] = fma2(p, b3.x, acc[0][0]); acc[0][1] = fma2(p, b3.y, acc[0][1]);
            p = pack2(a1.x, a1.x); acc[1][0] = fma2(p, b0.x, acc[1][0]); acc[1][1] = fma2(p, b0.y, acc[1][1]);
            p = pack2(a1.y, a1.y); acc[1][0] = fma2(p, b1.x, acc[1][0]); acc[1][1] = fma2(p, b1.y, acc[1][1]);
            p = pack2(a1.z, a1.z); acc[1][0] = fma2(p, b2.x, acc[1][0]); acc[1][1] = fma2(p, b2.y, acc[1][1]);
            p = pack2(a1.w, a1.w); acc[1][0] = fma2(p, b3.x, acc[1][0]); acc[1][1] = fma2(p, b3.y, acc[1][1]);
            p = pack2(a2.x, a2.x); acc[2][0] = fma2(p, b0.x, acc[2][0]); acc[2][1] = fma2(p, b0.y, acc[2][1]);
            p = pack2(a2.y, a2.y); acc[2][0] = fma2(p, b1.x, acc[2][0]); acc[2][1] = fma2(p, b1.y, acc[2][1]);
            p = pack2(a2.z, a2.z); acc[2][0] = fma2(p, b2.x, acc[2][0]); acc[2][1] = fma2(p, b2.y, acc[2][1]);
            p = pack2(a2.w, a2.w); acc[2][0] = fma2(p, b3.x, acc[2][0]); acc[2][1] = fma2(p, b3.y, acc[2][1]);
            p = pack2(a3.x, a3.x); acc[3][0] = fma2(p, b0.x, acc[3][0]); acc[3][1] = fma2(p, b0.y, acc[3][1]);
            p = pack2(a3.y, a3.y); acc[3][0] = fma2(p, b1.x, acc[3][0]); acc[3][1] = fma2(p, b1.y, acc[3][1]);
            p = pack2(a3.z, a3.z); acc[3][0] = fma2(p, b2.x, acc[3][0]); acc[3][1] = fma2(p, b2.y, acc[3][1]);
            p = pack2(a3.w, a3.w); acc[3][0] = fma2(p, b3.x, acc[3][0]); acc[3][1] = fma2(p, b3.y, acc[3][1]);
        }
        #pragma unroll
        for (int r = 0; r < 4; r++) {
            ulonglong2 o; o.x = acc[r][0]; o.y = acc[r][1];
            *(ulonglong2*)(sC + (j0 + r) * SP + t0) = o;
        }
    }
}

// sKQ[s*SP + t] = sum_i sK[i*SP + s] * sQ[i*SP + t]  (packed over t; chain over i ascending)
__device__ __forceinline__ void gemm_kq(const float* __restrict__ sK,
                                        const float* __restrict__ sQ,
                                        float* __restrict__ sKQ) {
    for (int tile = threadIdx.x; tile < 34 * 17; tile += NT) {
        int s0 = (tile / 17) << 1;
        int t0 = (tile % 17) << 2;
        u64 acc[2][2];
        acc[0][0] = acc[0][1] = acc[1][0] = acc[1][1] = 0ull;
        #pragma unroll 4
        for (int i = 0; i < HH; i++) {
            float a0 = sK[i * SP + s0 + 0];
            float a1 = sK[i * SP + s0 + 1];
            ulonglong2 q = *(const ulonglong2*)(sQ + i * SP + t0);
            u64 aa0 = pack2(a0, a0), aa1 = pack2(a1, a1);
            acc[0][0] = fma2(aa0, q.x, acc[0][0]); acc[0][1] = fma2(aa0, q.y, acc[0][1]);
            acc[1][0] = fma2(aa1, q.x, acc[1][0]); acc[1][1] = fma2(aa1, q.y, acc[1][1]);
        }
        ulonglong2 o0; o0.x = acc[0][0]; o0.y = acc[0][1];
        ulonglong2 o1; o1.x = acc[1][0]; o1.y = acc[1][1];
        *(ulonglong2*)(sKQ + (s0 + 0) * SP + t0) = o0;
        *(ulonglong2*)(sKQ + (s0 + 1) * SP + t0) = o1;
    }
}

// row-wise softmax over t in [0,65), accurate expf + true division
__device__ __forceinline__ void softmax_rows(float* __restrict__ sKQ) {
    int warp = threadIdx.x >> 5, lane = threadIdx.x & 31;
    for (int s = warp; s < SS; s += NT / 32) {
        float* row = sKQ + s * SP;
        float v0 = row[lane], v1 = row[lane + 32], v2 = row[64];
        float m = fmaxf(fmaxf(v0, v1), v2);
        #pragma unroll
        for (int o = 16; o; o >>= 1) m = fmaxf(m, __shfl_xor_sync(0xffffffffu, m, o));
        float e0 = expf(v0 - m), e1 = expf(v1 - m), e2 = expf(v2 - m);
        float sum = e0 + e1;
        #pragma unroll
        for (int o = 16; o; o >>= 1) sum += __shfl_xor_sync(0xffffffffu, sum, o);
        float denom = sum + e2;
        row[lane] = e0 / denom;
        row[lane + 32] = e1 / denom;
        if (lane == 0) { row[64] = e2 / denom; row[65] = 0.f; row[66] = 0.f; row[67] = 0.f; }
    }
    if (threadIdx.x < 3 * SP) sKQ[SS * SP + threadIdx.x] = 0.f;  // zero rows 65..67
}

// sO[s*HH + i] = sum_t sKQ[s*SP + t] * sV[i*SP + t]  (in-order over t; pads zero)
__device__ __forceinline__ void gemm_O(const float* __restrict__ sKQ,
                                       const float* __restrict__ sV,
                                       float* __restrict__ sO) {
    for (int tile = threadIdx.x; tile < 17 * 32; tile += NT) {
        int s0 = (tile / 32) << 2;
        int i0 = (tile % 32) << 2;
        float4 acc0 = {0,0,0,0}, acc1 = {0,0,0,0}, acc2 = {0,0,0,0}, acc3 = {0,0,0,0};
        #pragma unroll 4
        for (int t = 0; t < SP; t += 4) {
            float4 p0 = *(const float4*)(sKQ + (s0 + 0) * SP + t);
            float4 p1 = *(const float4*)(sKQ + (s0 + 1) * SP + t);
            float4 p2 = *(const float4*)(sKQ + (s0 + 2) * SP + t);
            float4 p3 = *(const float4*)(sKQ + (s0 + 3) * SP + t);
            float4 v0 = *(const float4*)(sV + (i0 + 0) * SP + t);
            float4 v1 = *(const float4*)(sV + (i0 + 1) * SP + t);
            float4 v2 = *(const float4*)(sV + (i0 + 2) * SP + t);
            float4 v3 = *(const float4*)(sV + (i0 + 3) * SP + t);
            acc0.x = dot4(p0, v0, acc0.x); acc0.y = dot4(p0, v1, acc0.y);
            acc0.z = dot4(p0, v2, acc0.z); acc0.w = dot4(p0, v3, acc0.w);
            acc1.x = dot4(p1, v0, acc1.x); acc1.y = dot4(p1, v1, acc1.y);
            acc1.z = dot4(p1, v2, acc1.z); acc1.w = dot4(p1, v3, acc1.w);
            acc2.x = dot4(p2, v0, acc2.x); acc2.y = dot4(p2, v1, acc2.y);
            acc2.z = dot4(p2, v2, acc2.z); acc2.w = dot4(p2, v3, acc2.w);
            acc3.x = dot4(p3, v0, acc3.x); acc3.y = dot4(p3, v1, acc3.y);
            acc3.z = dot4(p3, v2, acc3.z); acc3.w = dot4(p3, v3, acc3.w);
        }
        *(float4*)(sO + (s0 + 0) * HH + i0) = acc0;
        *(float4*)(sO + (s0 + 1) * HH + i0) = acc1;
        *(float4*)(sO + (s0 + 2) * HH + i0) = acc2;
        *(float4*)(sO + (s0 + 3) * HH + i0) = acc3;
    }
}

// sZ[s*HH + j] (head0: =, head1: continue chain) sum_i sO[s*HH+i] * L[i*HH+j]
// Store/reload of fp32 partials is exact -> bit-identical to a single 256-deep chain.
template <int FIRST>
__device__ __forceinline__ void gemm_Z(const float* __restrict__ sO,
                                       const float* __restrict__ L,
                                       float* __restrict__ sZ) {
    for (int tile = threadIdx.x; tile < 17 * 32; tile += NT) {
        int s0 = (tile / 32) << 2;
        int j0 = (tile % 32) << 2;
        u64 acc[4][2];
        #pragma unroll
        for (int r = 0; r < 4; r++) {
            if (FIRST) { acc[r][0] = 0ull; acc[r][1] = 0ull; }
            else {
                ulonglong2 z = *(const ulonglong2*)(sZ + (s0 + r) * HH + j0);
                acc[r][0] = z.x; acc[r][1] = z.y;
            }
        }
        #pragma unroll 2
        for (int i = 0; i < HH; i += 4) {
            float4 o0 = *(const float4*)(sO + (s0 + 0) * HH + i);
            float4 o1 = *(const float4*)(sO + (s0 + 1) * HH + i);
            float4 o2 = *(const float4*)(sO + (s0 + 2) * HH + i);
            float4 o3 = *(const float4*)(sO + (s0 + 3) * HH + i);
            ulonglong2 l0 = *(const ulonglong2*)(L + (i + 0) * HH + j0);
            ulonglong2 l1 = *(const ulonglong2*)(L + (i + 1) * HH + j0);
            ulonglong2 l2 = *(const ulonglong2*)(L + (i + 2) * HH + j0);
            ulonglong2 l3 = *(const ulonglong2*)(L + (i + 3) * HH + j0);
            u64 p;
            p = pack2(o0.x, o0.x); acc[0][0] = fma2(p, l0.x, acc[0][0]); acc[0][1] = fma2(p, l0.y, acc[0][1]);
            p = pack2(o0.y, o0.y); acc[0][0] = fma2(p, l1.x, acc[0][0]); acc[0][1] = fma2(p, l1.y, acc[0][1]);
            p = pack2(o0.z, o0.z); acc[0][0] = fma2(p, l2.x, acc[0][0]); acc[0][1] = fma2(p, l2.y, acc[0][1]);
            p = pack2(o0.w, o0.w); acc[0][0] = fma2(p, l3.x, acc[0][0]); acc[0][1] = fma2(p, l3.y, acc[0][1]);
            p = pack2(o1.x, o1.x); acc[1][0] = fma2(p, l0.x, acc[1][0]); acc[1][1] = fma2(p, l0.y, acc[1][1]);
            p = pack2(o1.y, o1.y); acc[1][0] = fma2(p, l1.x, acc[1][0]); acc[1][1] = fma2(p, l1.y, acc[1][1]);
            p = pack2(o1.z, o1.z); acc[1][0] = fma2(p, l2.x, acc[1][0]); acc[1][1] = fma2(p, l2.y, acc[1][1]);
            p = pack2(o1.w, o1.w); acc[1][0] = fma2(p, l3.x, acc[1][0]); acc[1][1] = fma2(p, l3.y, acc[1][1]);
            p = pack2(o2.x, o2.x); acc[2][0] = fma2(p, l0.x, acc[2][0]); acc[2][1] = fma2(p, l0.y, acc[2][1]);
            p = pack2(o2.y, o2.y); acc[2][0] = fma2(p, l1.x, acc[2][0]); acc[2][1] = fma2(p, l1.y, acc[2][1]);
            p = pack2(o2.z, o2.z); acc[2][0] = fma2(p, l2.x, acc[2][0]); acc[2][1] = fma2(p, l2.y, acc[2][1]);
            p = pack2(o2.w, o2.w); acc[2][0] = fma2(p, l3.x, acc[2][0]); acc[2][1] = fma2(p, l3.y, acc[2][1]);
            p = pack2(o3.x, o3.x); acc[3][0] = fma2(p, l0.x, acc[3][0]); acc[3][1] = fma2(p, l0.y, acc[3][1]);
            p = pack2(o3.y, o3.y); acc[3][0] = fma2(p, l1.x, acc[3][0]); acc[3][1] = fma2(p, l1.y, acc[3][1]);
            p = pack2(o3.z, o3.z); acc[3][0] = fma2(p, l2.x, acc[3][0]); acc[3][1] = fma2(p, l2.y, acc[3][1]);
            p = pack2(o3.w, o3.w); acc[3][0] = fma2(p, l3.x, acc[3][0]); acc[3][1] = fma2(p, l3.y, acc[3][1]);
        }
        #pragma unroll
        for (int r = 0; r < 4; r++) {
            ulonglong2 o; o.x = acc[r][0]; o.y = acc[r][1];
            *(ulonglong2*)(sZ + (s0 + r) * HH + j0) = o;
        }
    }
}

// smem layout (floats):
//  sY  @     0 : 8704  (128 x 68)
//  sK  @  8704 : 8704  (K; then O)
//  sQ  @ 17408 : 8704  (Q; then V; then q2)
//  sZ  @ 26112 : 8704  (68 x 128)
//  sKQ @ 34816 : 4624  (68 x 68)
//  sEX @ 39440 : 1024
#define SMEM_FLOATS 40464

__global__ void __launch_bounds__(NT, 1) board_kernel(
    const float* __restrict__ inp, const float* __restrict__ emb,
    const float* __restrict__ wk11, const float* __restrict__ wq11, const float* __restrict__ wv11,
    const float* __restrict__ wk12, const float* __restrict__ wq12, const float* __restrict__ wv12,
    const float* __restrict__ L1,
    const float* __restrict__ wk21, const float* __restrict__ wq21, const float* __restrict__ wv21,
    const float* __restrict__ wk22, const float* __restrict__ wq22, const float* __restrict__ wv22,
    const float* __restrict__ L2, const float* __restrict__ L3, const float* __restrict__ L4,
    float* __restrict__ out) {
    extern __shared__ float sm[];
    float* sY  = sm;
    float* sK  = sm + 8704;     // K, then O
    float* sQ  = sm + 17408;    // Q, then V, then q2
    float* sZ  = sm + 26112;    // 68 x 128
    float* sKQ = sm + 34816;
    float* sEX = sm + 39440;

    float* sc   = sEX;          // 128 (layer-2 c = Wk2 @ y64)
    float* sw   = sEX + 128;    // 72 (softmax row)
    float* syw  = sEX + 200;    // 128
    float* satt = sEX + 328;    // 256
    float* sh2  = sEX + 584;    // 128
    float* sh3  = sEX + 712;    // 64

    const int b = blockIdx.x;
    const int tid = threadIdx.x;
    const float* x = inp + (size_t)b * 64;

    // Y[j][s] = emb[j][s] * x[s], x[64]=1; padding cols zero.
    for (int idx = tid; idx < HH * SP; idx += NT) {
        int j = idx / SP, s = idx - j * SP;
        float v = 0.f;
        if (s < 64)       v = emb[j * 65 + s] * x[s];
        else if (s == 64) v = emb[j * 65 + 64];
        sY[idx] = v;
    }
    __syncthreads();

    // ---- layer 1: two full attentions (explicit k, q — reference decomposition) ----
    #pragma unroll 1
    for (int a = 0; a < 2; a++) {
        const float* Wk = (a == 0) ? wk11 : wk12;
        const float* Wq = (a == 0) ? wq11 : wq12;
        const float* Wv = (a == 0) ? wv11 : wv12;
        gemm_A(Wk, sY, sK);              // K = Wk @ Y
        gemm_A(Wq, sY, sQ);              // Q = Wq @ Y
        __syncthreads();
        gemm_kq(sK, sQ, sKQ);            // KQ = K^T @ Q
        __syncthreads();
        softmax_rows(sKQ);               // softmax rows
        gemm_A(Wv, sY, sQ);              // V = Wv @ Y (overwrites Q)
        __syncthreads();
        gemm_O(sKQ, sQ, sK);             // O = SM @ V^T (overwrites K)
        __syncthreads();
        if (a == 0) gemm_Z<1>(sK, L1,             sZ);  // Z  = O0 @ L1[:128]
        else        gemm_Z<0>(sK, L1 + HH * HH,   sZ);  // Z += O1 @ L1[128:], chain continues
        __syncthreads();
    }

    // tanh + transpose: Y2[j][s] = tanh(Z[s][j])
    for (int idx = tid; idx < HH * SP; idx += NT) {
        int j = idx / SP, s = idx - j * SP;
        sY[idx] = (s < SS) ? tanhf(sZ[s * HH + j]) : 0.f;
    }
    __syncthreads();

    // ---- layer 2: only row s=64 of att needed, logits via explicit q2 GEMM ----
    int lane = tid & 31;
    #pragma unroll 1
    for (int a2 = 0; a2 < 2; a2++) {
        const float* Wk = (a2 == 0) ? wk21 : wk22;
        const float* Wq = (a2 == 0) ? wq21 : wq22;
        const float* Wv = (a2 == 0) ? wv21 : wv22;
        gemm_A(Wq, sY, sQ);                   // q2 = Wq @ Y2 (full, ref decomposition)
        if (tid < HH) {                       // c[i] = sum_j Wk[i][j] * y64[j]  (in-order)
            float acc = 0.f;
            #pragma unroll 8
            for (int j = 0; j < HH; j++)
                acc = fmaf(Wk[tid * HH + j], sY[j * SP + 64], acc);
            sc[tid] = acc;
        }
        __syncthreads();
        if (tid < SS) {                       // logits[t] = sum_i c[i] * q2[i][t]  (in-order)
            float acc = 0.f;
            #pragma unroll 8
            for (int i = 0; i < HH; i++)
                acc = fmaf(sc[i], sQ[i * SP + tid], acc);
            sw[tid] = acc;
        }
        __syncthreads();
        if (tid < 32) {                       // softmax (single row)
            float v0 = sw[lane], v1 = sw[lane + 32], v2 = sw[64];
            float m = fmaxf(fmaxf(v0, v1), v2);
            #pragma unroll
            for (int o = 16; o; o >>= 1) m = fmaxf(m, __shfl_xor_sync(0xffffffffu, m, o));
            float e0 = expf(v0 - m), e1 = expf(v1 - m), e2 = expf(v2 - m);
            float sum = e0 + e1;
            #pragma unroll
            for (int o = 16; o; o >>= 1) sum += __shfl_xor_sync(0xffffffffu, sum, o);
            float denom = sum + e2;
            sw[lane] = e0 / denom;
            sw[lane + 32] = e1 / denom;
            if (lane == 0) { sw[64] = e2 / denom; sw[65] = 0.f; sw[66] = 0.f; sw[67] = 0.f; }
        }
        __syncthreads();
        if (tid < HH) {                       // yw[j] = sum_t w[t] * Y2[j][t]
            float acc = 0.f;
            #pragma unroll
            for (int t = 0; t < SP; t += 4) {
                float4 y4 = *(const float4*)(sY + tid * SP + t);
                float4 w4 = *(const float4*)(sw + t);
                acc = dot4(y4, w4, acc);
            }
            syw[tid] = acc;
        }
        __syncthreads();
        if (tid < HH) {                       // att64[i] = sum_j Wv[i][j] * yw[j]
            float acc = 0.f;
            #pragma unroll 8
            for (int j = 0; j < HH; j += 4) {
                float4 w4 = *(const float4*)(Wv + tid * HH + j);
                float4 y4 = *(const float4*)(syw + j);
                acc = dot4(w4, y4, acc);
            }
            satt[a2 * HH + tid] = acc;
        }
        __syncthreads();
    }

    // head: h2 = tanh(cat(att) @ L2), h3 = tanh(h2 @ L3), score = h3 @ L4
    if (tid < HH) {
        float acc = 0.f;
        #pragma unroll 8
        for (int i = 0; i < 2 * HH; i++)
            acc = fmaf(satt[i], L2[i * HH + tid], acc);
        sh2[tid] = tanhf(acc);
    }
    __syncthreads();
    if (tid < 64) {
        float acc = 0.f;
        #pragma unroll 8
        for (int j = 0; j < HH; j++)
            acc = fmaf(sh2[j], L3[j * 64 + tid], acc);
        sh3[tid] = tanhf(acc);
    }
    __syncthreads();
    if (tid == 0) {
        float acc = 0.f;
        #pragma unroll
        for (int m = 0; m < 64; m++) acc = fmaf(sh3[m], L4[m], acc);
        out[b] = acc;
    }
}

extern "C" void kernel_launch(void* const* d_in, const int* in_sizes, int n_in,
                              void* d_out, int out_size) {
    const float* inputs = (const float*)d_in[0];
    const float* emb    = (const float*)d_in[1];
    const float* wk11   = (const float*)d_in[2];
    const float* wq11   = (const float*)d_in[3];
    const float* wv11   = (const float*)d_in[4];
    const float* wk12   = (const float*)d_in[5];
    const float* wq12   = (const float*)d_in[6];
    const float* wv12   = (const float*)d_in[7];
    const float* L1     = (const float*)d_in[8];
    const float* wk21   = (const float*)d_in[9];
    const float* wq21   = (const float*)d_in[10];
    const float* wv21   = (const float*)d_in[11];
    const float* wk22   = (const float*)d_in[12];
    const float* wq22   = (const float*)d_in[13];
    const float* wv22   = (const float*)d_in[14];
    const float* L2     = (const float*)d_in[15];
    const float* L3     = (const float*)d_in[16];
    const float* L4     = (const float*)d_in[17];
    (void)n_in; (void)in_sizes;

    int B = out_size;  // one score per board (8192)

    size_t smem = SMEM_FLOATS * sizeof(float);
    cudaFuncSetAttribute(board_kernel, cudaFuncAttributeMaxDynamicSharedMemorySize, (int)smem);

    board_kernel<<<B, NT, smem>>>(inputs, emb,
                                  wk11, wq11, wv11, wk12, wq12, wv12, L1,
                                  wk21, wq21, wv21, wk22, wq22, wv22, L2, L3, L4,
                                  (float*)d_out);
}

// round 6
// speedup vs baseline: 1.2627x; 1.2627x over previous
#include <cuda_runtime.h>
#include <math.h>

#define HH 128
#define SS 65
#define SP 68          // padded S (stride), cols 65..67 kept zero
#define NT 512

typedef unsigned long long u64;

// ---------- f32x2 packed helpers (per-lane IEEE fp32, identical rounding) ----------
__device__ __forceinline__ u64 pack2(float lo, float hi) {
    u64 r; asm("mov.b64 %0, {%1, %2};" : "=l"(r) : "f"(lo), "f"(hi)); return r;
}
__device__ __forceinline__ u64 fma2(u64 a, u64 b, u64 c) {
    u64 d; asm("fma.rn.f32x2 %0, %1, %2, %3;" : "=l"(d) : "l"(a), "l"(b), "l"(c)); return d;
}

__device__ __forceinline__ float dot4(const float4& a, const float4& b, float acc) {
    acc = fmaf(a.x, b.x, acc);
    acc = fmaf(a.y, b.y, acc);
    acc = fmaf(a.z, b.z, acc);
    acc = fmaf(a.w, b.w, acc);
    return acc;
}

// sC[j*SP + t] = sum_k A[j*HH + k] * sB[k*SP + t]
// Main pass: exactly 512 tiles (32 j-strips x 16 t-tiles, t<64), one wavefront.
// Tail: col 64 computed by 128 threads (in-order k chain), cols 65..67 zeroed.
__device__ __forceinline__ void gemm_A(const float* __restrict__ A,
                                       const float* __restrict__ sB,
                                       float* __restrict__ sC) {
    {
        int tid = threadIdx.x;
        int j0 = (tid >> 4) << 2;        // 0..124
        int t0 = (tid & 15) << 2;        // 0..60
        u64 acc[4][2];
        #pragma unroll
        for (int r = 0; r < 4; r++) { acc[r][0] = 0ull; acc[r][1] = 0ull; }
        #pragma unroll 2
        for (int k = 0; k < HH; k += 4) {
            float4 a0 = *(const float4*)(A + (j0 + 0) * HH + k);
            float4 a1 = *(const float4*)(A + (j0 + 1) * HH + k);
            float4 a2 = *(const float4*)(A + (j0 + 2) * HH + k);
            float4 a3 = *(const float4*)(A + (j0 + 3) * HH + k);
            ulonglong2 b0 = *(const ulonglong2*)(sB + (k + 0) * SP + t0);
            ulonglong2 b1 = *(const ulonglong2*)(sB + (k + 1) * SP + t0);
            ulonglong2 b2 = *(const ulonglong2*)(sB + (k + 2) * SP + t0);
            ulonglong2 b3 = *(const ulonglong2*)(sB + (k + 3) * SP + t0);
            u64 p;
            p = pack2(a0.x, a0.x); acc[0][0] = fma2(p, b0.x, acc[0][0]); acc[0][1] = fma2(p, b0.y, acc[0][1]);
            p = pack2(a0.y, a0.y); acc[0][0] = fma2(p, b1.x, acc[0][0]); acc[0][1] = fma2(p, b1.y, acc[0][1]);
            p = pack2(a0.z, a0.z); acc[0][0] = fma2(p, b2.x, acc[0][0]); acc[0][1] = fma2(p, b2.y, acc[0][1]);
            p = pack2(a0.w, a0.w); acc[0][0] = fma2(p, b3.x, acc[0][0]); acc[0][1] = fma2(p, b3.y, acc[0][1]);
            p = pack2(a1.x, a1.x); acc[1][0] = fma2(p, b0.x, acc[1][0]); acc[1][1] = fma2(p, b0.y, acc[1][1]);
            p = pack2(a1.y, a1.y); acc[1][0] = fma2(p, b1.x, acc[1][0]); acc[1][1] = fma2(p, b1.y, acc[1][1]);
            p = pack2(a1.z, a1.z); acc[1][0] = fma2(p, b2.x, acc[1][0]); acc[1][1] = fma2(p, b2.y, acc[1][1]);
            p = pack2(a1.w, a1.w); acc[1][0] = fma2(p, b3.x, acc[1][0]); acc[1][1] = fma2(p, b3.y, acc[1][1]);
            p = pack2(a2.x, a2.x); acc[2][0] = fma2(p, b0.x, acc[2][0]); acc[2][1] = fma2(p, b0.y, acc[2][1]);
            p = pack2(a2.y, a2.y); acc[2][0] = fma2(p, b1.x, acc[2][0]); acc[2][1] = fma2(p, b1.y, acc[2][1]);
            p = pack2(a2.z, a2.z); acc[2][0] = fma2(p, b2.x, acc[2][0]); acc[2][1] = fma2(p, b2.y, acc[2][1]);
            p = pack2(a2.w, a2.w); acc[2][0] = fma2(p, b3.x, acc[2][0]); acc[2][1] = fma2(p, b3.y, acc[2][1]);
            p = pack2(a3.x, a3.x); acc[3][0] = fma2(p, b0.x, acc[3][0]); acc[3][1] = fma2(p, b0.y, acc[3][1]);
            p = pack2(a3.y, a3.y); acc[3][0] = fma2(p, b1.x, acc[3][0]); acc[3][1] = fma2(p, b1.y, acc[3][1]);
            p = pack2(a3.z, a3.z); acc[3][0] = fma2(p, b2.x, acc[3][0]); acc[3][1] = fma2(p, b2.y, acc[3][1]);
            p = pack2(a3.w, a3.w); acc[3][0] = fma2(p, b3.x, acc[3][0]); acc[3][1] = fma2(p, b3.y, acc[3][1]);
        }
        #pragma unroll
        for (int r = 0; r < 4; r++) {
            ulonglong2 o; o.x = acc[r][0]; o.y = acc[r][1];
            *(ulonglong2*)(sC + (j0 + r) * SP + t0) = o;
        }
    }
    // tail: t = 64 (real), 65..67 zero pads
    if (threadIdx.x < HH) {
        int j = threadIdx.x;
        float acc = 0.f;
        #pragma unroll 4
        for (int k = 0; k < HH; k += 4) {
            float4 a = *(const float4*)(A + j * HH + k);
            acc = fmaf(a.x, sB[(k + 0) * SP + 64], acc);
            acc = fmaf(a.y, sB[(k + 1) * SP + 64], acc);
            acc = fmaf(a.z, sB[(k + 2) * SP + 64], acc);
            acc = fmaf(a.w, sB[(k + 3) * SP + 64], acc);
        }
        sC[j * SP + 64] = acc;
        sC[j * SP + 65] = 0.f;
        sC[j * SP + 66] = 0.f;
        sC[j * SP + 67] = 0.f;
    }
}

// sKQ[s*SP + t] = sum_i sK[i*SP + s] * sQ[i*SP + t]
// Main: exactly 512 tiles (32 s-strips of 2 x 16 t-tiles, s<64, t<64).
// Tail: row s=64 (t 0..64) and col t=64 (s 0..63): 129 scalar in-order dots.
__device__ __forceinline__ void gemm_kq(const float* __restrict__ sK,
                                        const float* __restrict__ sQ,
                                        float* __restrict__ sKQ) {
    {
        int tid = threadIdx.x;
        int s0 = (tid >> 4) << 1;        // 0..62
        int t0 = (tid & 15) << 2;        // 0..60
        u64 acc[2][2];
        acc[0][0] = acc[0][1] = acc[1][0] = acc[1][1] = 0ull;
        #pragma unroll 4
        for (int i = 0; i < HH; i++) {
            float a0 = sK[i * SP + s0 + 0];
            float a1 = sK[i * SP + s0 + 1];
            ulonglong2 q = *(const ulonglong2*)(sQ + i * SP + t0);
            u64 aa0 = pack2(a0, a0), aa1 = pack2(a1, a1);
            acc[0][0] = fma2(aa0, q.x, acc[0][0]); acc[0][1] = fma2(aa0, q.y, acc[0][1]);
            acc[1][0] = fma2(aa1, q.x, acc[1][0]); acc[1][1] = fma2(aa1, q.y, acc[1][1]);
        }
        ulonglong2 o0; o0.x = acc[0][0]; o0.y = acc[0][1];
        ulonglong2 o1; o1.x = acc[1][0]; o1.y = acc[1][1];
        *(ulonglong2*)(sKQ + (s0 + 0) * SP + t0) = o0;
        *(ulonglong2*)(sKQ + (s0 + 1) * SP + t0) = o1;
    }
    // tail: (s=64, t=0..64) and (s=0..63, t=64)
    if (threadIdx.x < 129) {
        int id = threadIdx.x;
        int s = (id < 65) ? 64 : (id - 65);
        int t = (id < 65) ? id : 64;
        float acc = 0.f;
        #pragma unroll 8
        for (int i = 0; i < HH; i++)
            acc = fmaf(sK[i * SP + s], sQ[i * SP + t], acc);
        sKQ[s * SP + t] = acc;
    }
}

// row-wise softmax over t in [0,65); zeroes pad cols 65..67 and pad rows 65..67
__device__ __forceinline__ void softmax_rows(float* __restrict__ sKQ) {
    int warp = threadIdx.x >> 5, lane = threadIdx.x & 31;
    for (int s = warp; s < SS; s += NT / 32) {
        float* row = sKQ + s * SP;
        float v0 = row[lane], v1 = row[lane + 32], v2 = row[64];
        float m = fmaxf(fmaxf(v0, v1), v2);
        #pragma unroll
        for (int o = 16; o; o >>= 1) m = fmaxf(m, __shfl_xor_sync(0xffffffffu, m, o));
        float e0 = expf(v0 - m), e1 = expf(v1 - m), e2 = expf(v2 - m);
        float sum = e0 + e1;
        #pragma unroll
        for (int o = 16; o; o >>= 1) sum += __shfl_xor_sync(0xffffffffu, sum, o);
        float denom = sum + e2;
        row[lane] = e0 / denom;
        row[lane + 32] = e1 / denom;
        if (lane == 0) { row[64] = e2 / denom; row[65] = 0.f; row[66] = 0.f; row[67] = 0.f; }
    }
    if (threadIdx.x < 3 * SP) sKQ[SS * SP + threadIdx.x] = 0.f;  // zero rows 65..67
}

// sO[s*HH + i] = sum_t sKQ[s*SP + t] * sV[i*SP + t]
// Main: exactly 512 tiles (16 s-strips x 32 i-tiles, s<64). Tail: row s=64.
__device__ __forceinline__ void gemm_O(const float* __restrict__ sKQ,
                                       const float* __restrict__ sV,
                                       float* __restrict__ sO) {
    {
        int tid = threadIdx.x;
        int s0 = (tid >> 5) << 2;        // 0..60
        int i0 = (tid & 31) << 2;        // 0..124
        float4 acc0 = {0,0,0,0}, acc1 = {0,0,0,0}, acc2 = {0,0,0,0}, acc3 = {0,0,0,0};
        #pragma unroll 4
        for (int t = 0; t < SP; t += 4) {
            float4 p0 = *(const float4*)(sKQ + (s0 + 0) * SP + t);
            float4 p1 = *(const float4*)(sKQ + (s0 + 1) * SP + t);
            float4 p2 = *(const float4*)(sKQ + (s0 + 2) * SP + t);
            float4 p3 = *(const float4*)(sKQ + (s0 + 3) * SP + t);
            float4 v0 = *(const float4*)(sV + (i0 + 0) * SP + t);
            float4 v1 = *(const float4*)(sV + (i0 + 1) * SP + t);
            float4 v2 = *(const float4*)(sV + (i0 + 2) * SP + t);
            float4 v3 = *(const float4*)(sV + (i0 + 3) * SP + t);
            acc0.x = dot4(p0, v0, acc0.x); acc0.y = dot4(p0, v1, acc0.y);
            acc0.z = dot4(p0, v2, acc0.z); acc0.w = dot4(p0, v3, acc0.w);
            acc1.x = dot4(p1, v0, acc1.x); acc1.y = dot4(p1, v1, acc1.y);
            acc1.z = dot4(p1, v2, acc1.z); acc1.w = dot4(p1, v3, acc1.w);
            acc2.x = dot4(p2, v0, acc2.x); acc2.y = dot4(p2, v1, acc2.y);
            acc2.z = dot4(p2, v2, acc2.z); acc2.w = dot4(p2, v3, acc2.w);
            acc3.x = dot4(p3, v0, acc3.x); acc3.y = dot4(p3, v1, acc3.y);
            acc3.z = dot4(p3, v2, acc3.z); acc3.w = dot4(p3, v3, acc3.w);
        }
        *(float4*)(sO + (s0 + 0) * HH + i0) = acc0;
        *(float4*)(sO + (s0 + 1) * HH + i0) = acc1;
        *(float4*)(sO + (s0 + 2) * HH + i0) = acc2;
        *(float4*)(sO + (s0 + 3) * HH + i0) = acc3;
    }
    // tail: s = 64
    if (threadIdx.x < HH) {
        int i = threadIdx.x;
        float acc = 0.f;
        #pragma unroll 4
        for (int t = 0; t < SP; t += 4) {
            float4 p = *(const float4*)(sKQ + 64 * SP + t);
            float4 v = *(const float4*)(sV + i * SP + t);
            acc = dot4(p, v, acc);
        }
        sO[64 * HH + i] = acc;
    }
}

// sZ[s*HH + j] (FIRST: =, else continue chain) sum_i sO[s*HH+i] * L[i*HH+j]
// Main: exactly 512 tiles (s<64). Tail: row s=64 (rows 65..67 never read).
template <int FIRST>
__device__ __forceinline__ void gemm_Z(const float* __restrict__ sO,
                                       const float* __restrict__ L,
                                       float* __restrict__ sZ) {
    {
        int tid = threadIdx.x;
        int s0 = (tid >> 5) << 2;        // 0..60
        int j0 = (tid & 31) << 2;        // 0..124
        u64 acc[4][2];
        #pragma unroll
        for (int r = 0; r < 4; r++) {
            if (FIRST) { acc[r][0] = 0ull; acc[r][1] = 0ull; }
            else {
                ulonglong2 z = *(const ulonglong2*)(sZ + (s0 + r) * HH + j0);
                acc[r][0] = z.x; acc[r][1] = z.y;
            }
        }
        #pragma unroll 2
        for (int i = 0; i < HH; i += 4) {
            float4 o0 = *(const float4*)(sO + (s0 + 0) * HH + i);
            float4 o1 = *(const float4*)(sO + (s0 + 1) * HH + i);
            float4 o2 = *(const float4*)(sO + (s0 + 2) * HH + i);
            float4 o3 = *(const float4*)(sO + (s0 + 3) * HH + i);
            ulonglong2 l0 = *(const ulonglong2*)(L + (i + 0) * HH + j0);
            ulonglong2 l1 = *(const ulonglong2*)(L + (i + 1) * HH + j0);
            ulonglong2 l2 = *(const ulonglong2*)(L + (i + 2) * HH + j0);
            ulonglong2 l3 = *(const ulonglong2*)(L + (i + 3) * HH + j0);
            u64 p;
            p = pack2(o0.x, o0.x); acc[0][0] = fma2(p, l0.x, acc[0][0]); acc[0][1] = fma2(p, l0.y, acc[0][1]);
            p = pack2(o0.y, o0.y); acc[0][0] = fma2(p, l1.x, acc[0][0]); acc[0][1] = fma2(p, l1.y, acc[0][1]);
            p = pack2(o0.z, o0.z); acc[0][0] = fma2(p, l2.x, acc[0][0]); acc[0][1] = fma2(p, l2.y, acc[0][1]);
            p = pack2(o0.w, o0.w); acc[0][0] = fma2(p, l3.x, acc[0][0]); acc[0][1] = fma2(p, l3.y, acc[0][1]);
            p = pack2(o1.x, o1.x); acc[1][0] = fma2(p, l0.x, acc[1][0]); acc[1][1] = fma2(p, l0.y, acc[1][1]);
            p = pack2(o1.y, o1.y); acc[1][0] = fma2(p, l1.x, acc[1][0]); acc[1][1] = fma2(p, l1.y, acc[1][1]);
            p = pack2(o1.z, o1.z); acc[1][0] = fma2(p, l2.x, acc[1][0]); acc[1][1] = fma2(p, l2.y, acc[1][1]);
            p = pack2(o1.w, o1.w); acc[1][0] = fma2(p, l3.x, acc[1][0]); acc[1][1] = fma2(p, l3.y, acc[1][1]);
            p = pack2(o2.x, o2.x); acc[2][0] = fma2(p, l0.x, acc[2][0]); acc[2][1] = fma2(p, l0.y, acc[2][1]);
            p = pack2(o2.y, o2.y); acc[2][0] = fma2(p, l1.x, acc[2][0]); acc[2][1] = fma2(p, l1.y, acc[2][1]);
            p = pack2(o2.z, o2.z); acc[2][0] = fma2(p, l2.x, acc[2][0]); acc[2][1] = fma2(p, l2.y, acc[2][1]);
            p = pack2(o2.w, o2.w); acc[2][0] = fma2(p, l3.x, acc[2][0]); acc[2][1] = fma2(p, l3.y, acc[2][1]);
            p = pack2(o3.x, o3.x); acc[3][0] = fma2(p, l0.x, acc[3][0]); acc[3][1] = fma2(p, l0.y, acc[3][1]);
            p = pack2(o3.y, o3.y); acc[3][0] = fma2(p, l1.x, acc[3][0]); acc[3][1] = fma2(p, l1.y, acc[3][1]);
            p = pack2(o3.z, o3.z); acc[3][0] = fma2(p, l2.x, acc[3][0]); acc[3][1] = fma2(p, l2.y, acc[3][1]);
            p = pack2(o3.w, o3.w); acc[3][0] = fma2(p, l3.x, acc[3][0]); acc[3][1] = fma2(p, l3.y, acc[3][1]);
        }
        #pragma unroll
        for (int r = 0; r < 4; r++) {
            ulonglong2 o; o.x = acc[r][0]; o.y = acc[r][1];
            *(ulonglong2*)(sZ + (s0 + r) * HH + j0) = o;
        }
    }
    // tail: s = 64
    if (threadIdx.x < HH) {
        int j = threadIdx.x;
        float acc = FIRST ? 0.f : sZ[64 * HH + j];
        #pragma unroll 8
        for (int i = 0; i < HH; i++)
            acc = fmaf(sO[64 * HH + i], L[i * HH + j], acc);
        sZ[64 * HH + j] = acc;
    }
}

// smem layout (floats):
//  sY  @     0 : 8704  (128 x 68)
//  sK  @  8704 : 8704  (K; then O)
//  sQ  @ 17408 : 8704  (Q; then V; then q2)
//  sZ  @ 26112 : 8704  (68 x 128)
//  sKQ @ 34816 : 4624  (68 x 68)
//  sEX @ 39440 : 1024
#define SMEM_FLOATS 40464

__global__ void __launch_bounds__(NT, 1) board_kernel(
    const float* __restrict__ inp, const float* __restrict__ emb,
    const float* __restrict__ wk11, const float* __restrict__ wq11, const float* __restrict__ wv11,
    const float* __restrict__ wk12, const float* __restrict__ wq12, const float* __restrict__ wv12,
    const float* __restrict__ L1,
    const float* __restrict__ wk21, const float* __restrict__ wq21, const float* __restrict__ wv21,
    const float* __restrict__ wk22, const float* __restrict__ wq22, const float* __restrict__ wv22,
    const float* __restrict__ L2, const float* __restrict__ L3, const float* __restrict__ L4,
    float* __restrict__ out) {
    extern __shared__ float sm[];
    float* sY  = sm;
    float* sK  = sm + 8704;     // K, then O
    float* sQ  = sm + 17408;    // Q, then V, then q2
    float* sZ  = sm + 26112;    // 68 x 128
    float* sKQ = sm + 34816;
    float* sEX = sm + 39440;

    float* sc   = sEX;          // 128 (layer-2 c = Wk2 @ y64)
    float* sw   = sEX + 128;    // 72 (softmax row)
    float* syw  = sEX + 200;    // 128
    float* satt = sEX + 328;    // 256
    float* sh2  = sEX + 584;    // 128
    float* sh3  = sEX + 712;    // 64

    const int b = blockIdx.x;
    const int tid = threadIdx.x;
    const float* x = inp + (size_t)b * 64;

    // Y[j][s] = emb[j][s] * x[s], x[64]=1; padding cols zero.
    for (int idx = tid; idx < HH * SP; idx += NT) {
        int j = idx / SP, s = idx - j * SP;
        float v = 0.f;
        if (s < 64)       v = emb[j * 65 + s] * x[s];
        else if (s == 64) v = emb[j * 65 + 64];
        sY[idx] = v;
    }
    __syncthreads();

    // ---- layer 1: two full attentions (explicit k, q — reference decomposition) ----
    #pragma unroll 1
    for (int a = 0; a < 2; a++) {
        const float* Wk = (a == 0) ? wk11 : wk12;
        const float* Wq = (a == 0) ? wq11 : wq12;
        const float* Wv = (a == 0) ? wv11 : wv12;
        gemm_A(Wk, sY, sK);              // K = Wk @ Y
        gemm_A(Wq, sY, sQ);              // Q = Wq @ Y
        __syncthreads();
        gemm_kq(sK, sQ, sKQ);            // KQ = K^T @ Q
        __syncthreads();
        softmax_rows(sKQ);               // softmax rows
        gemm_A(Wv, sY, sQ);              // V = Wv @ Y (overwrites Q)
        __syncthreads();
        gemm_O(sKQ, sQ, sK);             // O = SM @ V^T (overwrites K)
        __syncthreads();
        if (a == 0) gemm_Z<1>(sK, L1,           sZ);  // Z  = O0 @ L1[:128]
        else        gemm_Z<0>(sK, L1 + HH * HH, sZ);  // Z += O1 @ L1[128:], chain continues
        __syncthreads();
    }

    // tanh + transpose: Y2[j][s] = tanh(Z[s][j])
    for (int idx = tid; idx < HH * SP; idx += NT) {
        int j = idx / SP, s = idx - j * SP;
        sY[idx] = (s < SS) ? tanhf(sZ[s * HH + j]) : 0.f;
    }
    __syncthreads();

    // ---- layer 2: only row s=64 of att needed, logits via explicit q2 GEMM ----
    int lane = tid & 31;
    #pragma unroll 1
    for (int a2 = 0; a2 < 2; a2++) {
        const float* Wk = (a2 == 0) ? wk21 : wk22;
        const float* Wq = (a2 == 0) ? wq21 : wq22;
        const float* Wv = (a2 == 0) ? wv21 : wv22;
        gemm_A(Wq, sY, sQ);                   // q2 = Wq @ Y2 (full, ref decomposition)
        if (tid < HH) {                       // c[i] = sum_j Wk[i][j] * y64[j]  (in-order)
            float acc = 0.f;
            #pragma unroll 8
            for (int j = 0; j < HH; j++)
                acc = fmaf(Wk[tid * HH + j], sY[j * SP + 64], acc);
            sc[tid] = acc;
        }
        __syncthreads();
        if (tid < SS) {                       // logits[t] = sum_i c[i] * q2[i][t]  (in-order)
            float acc = 0.f;
            #pragma unroll 8
            for (int i = 0; i < HH; i++)
                acc = fmaf(sc[i], sQ[i * SP + tid], acc);
            sw[tid] = acc;
        }
        __syncthreads();
        if (tid < 32) {                       // softmax (single row)
            float v0 = sw[lane], v1 = sw[lane + 32], v2 = sw[64];
            float m = fmaxf(fmaxf(v0, v1), v2);
            #pragma unroll
            for (int o = 16; o; o >>= 1) m = fmaxf(m, __shfl_xor_sync(0xffffffffu, m, o));
            float e0 = expf(v0 - m), e1 = expf(v1 - m), e2 = expf(v2 - m);
            float sum = e0 + e1;
            #pragma unroll
            for (int o = 16; o; o >>= 1) sum += __shfl_xor_sync(0xffffffffu, sum, o);
            float denom = sum + e2;
            sw[lane] = e0 / denom;
            sw[lane + 32] = e1 / denom;
            if (lane == 0) { sw[64] = e2 / denom; sw[65] = 0.f; sw[66] = 0.f; sw[67] = 0.f; }
        }
        __syncthreads();
        if (tid < HH) {                       // yw[j] = sum_t w[t] * Y2[j][t]
            float acc = 0.f;
            #pragma unroll
            for (int t = 0; t < SP; t += 4) {
                float4 y4 = *(const float4*)(sY + tid * SP + t);
                float4 w4 = *(const float4*)(sw + t);
                acc = dot4(y4, w4, acc);
            }
            syw[tid] = acc;
        }
        __syncthreads();
        if (tid < HH) {                       // att64[i] = sum_j Wv[i][j] * yw[j]
            float acc = 0.f;
            #pragma unroll 8
            for (int j = 0; j < HH; j += 4) {
                float4 w4 = *(const float4*)(Wv + tid * HH + j);
                float4 y4 = *(const float4*)(syw + j);
                acc = dot4(w4, y4, acc);
            }
            satt[a2 * HH + tid] = acc;
        }
        __syncthreads();
    }

    // head: h2 = tanh(cat(att) @ L2), h3 = tanh(h2 @ L3), score = h3 @ L4
    if (tid < HH) {
        float acc = 0.f;
        #pragma unroll 8
        for (int i = 0; i < 2 * HH; i++)
            acc = fmaf(satt[i], L2[i * HH + tid], acc);
        sh2[tid] = tanhf(acc);
    }
    __syncthreads();
    if (tid < 64) {
        float acc = 0.f;
        #pragma unroll 8
        for (int j = 0; j < HH; j++)
            acc = fmaf(sh2[j], L3[j * 64 + tid], acc);
        sh3[tid] = tanhf(acc);
    }
    __syncthreads();
    if (tid == 0) {
        float acc = 0.f;
        #pragma unroll
        for (int m = 0; m < 64; m++) acc = fmaf(sh3[m], L4[m], acc);
        out[b] = acc;
    }
}

extern "C" void kernel_launch(void* const* d_in, const int* in_sizes, int n_in,
                              void* d_out, int out_size) {
    const float* inputs = (const float*)d_in[0];
    const float* emb    = (const float*)d_in[1];
    const float* wk11   = (const float*)d_in[2];
    const float* wq11   = (const float*)d_in[3];
    const float* wv11   = (const float*)d_in[4];
    const float* wk12   = (const float*)d_in[5];
    const float* wq12   = (const float*)d_in[6];
    const float* wv12   = (const float*)d_in[7];
    const float* L1     = (const float*)d_in[8];
    const float* wk21   = (const float*)d_in[9];
    const float* wq21   = (const float*)d_in[10];
    const float* wv21   = (const float*)d_in[11];
    const float* wk22   = (const float*)d_in[12];
    const float* wq22   = (const float*)d_in[13];
    const float* wv22   = (const float*)d_in[14];
    const float* L2     = (const float*)d_in[15];
    const float* L3     = (const float*)d_in[16];
    const float* L4     = (const float*)d_in[17];
    (void)n_in; (void)in_sizes;

    int B = out_size;  // one score per board (8192)

    size_t smem = SMEM_FLOATS * sizeof(float);
    cudaFuncSetAttribute(board_kernel, cudaFuncAttributeMaxDynamicSharedMemorySize, (int)smem);

    board_kernel<<<B, NT, smem>>>(inputs, emb,
                                  wk11, wq11, wv11, wk12, wq12, wv12, L1,
                                  wk21, wq21, wv21, wk22, wq22, wv22, L2, L3, L4,
                                  (float*)d_out);
}

// round 7
// speedup vs baseline: 1.3750x; 1.0890x over previous
#include <cuda_runtime.h>
#include <math.h>

#define HH 128
#define SS 65
#define SP 68          // padded S (stride), cols 65..67 kept zero
#define NT 512

typedef unsigned long long u64;

// ---------- f32x2 packed helpers (per-lane IEEE fp32, identical rounding) ----------
__device__ __forceinline__ u64 pack2(float lo, float hi) {
    u64 r; asm("mov.b64 %0, {%1, %2};" : "=l"(r) : "f"(lo), "f"(hi)); return r;
}
__device__ __forceinline__ u64 fma2(u64 a, u64 b, u64 c) {
    u64 d; asm("fma.rn.f32x2 %0, %1, %2, %3;" : "=l"(d) : "l"(a), "l"(b), "l"(c)); return d;
}

__device__ __forceinline__ float dot4(const float4& a, const float4& b, float acc) {
    acc = fmaf(a.x, b.x, acc);
    acc = fmaf(a.y, b.y, acc);
    acc = fmaf(a.z, b.z, acc);
    acc = fmaf(a.w, b.w, acc);
    return acc;
}

#define ACC_MAT(AR, Bx, By, Bz, Bw, ACC)                                              \
    do {                                                                              \
        u64 p_;                                                                       \
        p_ = pack2(AR.x, AR.x); ACC[0] = fma2(p_, Bx.x, ACC[0]); ACC[1] = fma2(p_, Bx.y, ACC[1]); \
        p_ = pack2(AR.y, AR.y); ACC[0] = fma2(p_, By.x, ACC[0]); ACC[1] = fma2(p_, By.y, ACC[1]); \
        p_ = pack2(AR.z, AR.z); ACC[0] = fma2(p_, Bz.x, ACC[0]); ACC[1] = fma2(p_, Bz.y, ACC[1]); \
        p_ = pack2(AR.w, AR.w); ACC[0] = fma2(p_, Bw.x, ACC[0]); ACC[1] = fma2(p_, Bw.y, ACC[1]); \
    } while (0)

// Fused 3-matrix projection: sK/sQ/sV[j*SP+t] = sum_k W{k,q,v}[j*HH+k] * sY[k*SP+t]
// ONE sweep of Y feeds all three. Per-output chain: k ascending (bit-identical).
__device__ __forceinline__ void gemm_KQV(
    const float* __restrict__ Wk, const float* __restrict__ Wq, const float* __restrict__ Wv,
    const float* __restrict__ sY,
    float* __restrict__ sK, float* __restrict__ sQ, float* __restrict__ sV) {
    {
        int tid = threadIdx.x;
        int j0 = (tid >> 4) << 2;        // 0..124
        int t0 = (tid & 15) << 2;        // 0..60
        u64 aK[4][2], aQ[4][2], aV[4][2];
        #pragma unroll
        for (int r = 0; r < 4; r++) {
            aK[r][0] = aK[r][1] = 0ull;
            aQ[r][0] = aQ[r][1] = 0ull;
            aV[r][0] = aV[r][1] = 0ull;
        }
        #pragma unroll 1
        for (int k = 0; k < HH; k += 4) {
            ulonglong2 b0 = *(const ulonglong2*)(sY + (k + 0) * SP + t0);
            ulonglong2 b1 = *(const ulonglong2*)(sY + (k + 1) * SP + t0);
            ulonglong2 b2 = *(const ulonglong2*)(sY + (k + 2) * SP + t0);
            ulonglong2 b3 = *(const ulonglong2*)(sY + (k + 3) * SP + t0);
            #pragma unroll
            for (int r = 0; r < 4; r++) {
                float4 ak = *(const float4*)(Wk + (j0 + r) * HH + k);
                ACC_MAT(ak, b0, b1, b2, b3, aK[r]);
                float4 aq = *(const float4*)(Wq + (j0 + r) * HH + k);
                ACC_MAT(aq, b0, b1, b2, b3, aQ[r]);
                float4 av = *(const float4*)(Wv + (j0 + r) * HH + k);
                ACC_MAT(av, b0, b1, b2, b3, aV[r]);
            }
        }
        #pragma unroll
        for (int r = 0; r < 4; r++) {
            ulonglong2 o;
            o.x = aK[r][0]; o.y = aK[r][1]; *(ulonglong2*)(sK + (j0 + r) * SP + t0) = o;
            o.x = aQ[r][0]; o.y = aQ[r][1]; *(ulonglong2*)(sQ + (j0 + r) * SP + t0) = o;
            o.x = aV[r][0]; o.y = aV[r][1]; *(ulonglong2*)(sV + (j0 + r) * SP + t0) = o;
        }
    }
    // tail: t = 64 for all three; pads 65..67 zeroed
    if (threadIdx.x < HH) {
        int j = threadIdx.x;
        float cK = 0.f, cQ = 0.f, cV = 0.f;
        #pragma unroll 4
        for (int k = 0; k < HH; k += 4) {
            float y0 = sY[(k + 0) * SP + 64];
            float y1 = sY[(k + 1) * SP + 64];
            float y2 = sY[(k + 2) * SP + 64];
            float y3 = sY[(k + 3) * SP + 64];
            float4 wk4 = *(const float4*)(Wk + j * HH + k);
            cK = fmaf(wk4.x, y0, cK); cK = fmaf(wk4.y, y1, cK);
            cK = fmaf(wk4.z, y2, cK); cK = fmaf(wk4.w, y3, cK);
            float4 wq4 = *(const float4*)(Wq + j * HH + k);
            cQ = fmaf(wq4.x, y0, cQ); cQ = fmaf(wq4.y, y1, cQ);
            cQ = fmaf(wq4.z, y2, cQ); cQ = fmaf(wq4.w, y3, cQ);
            float4 wv4 = *(const float4*)(Wv + j * HH + k);
            cV = fmaf(wv4.x, y0, cV); cV = fmaf(wv4.y, y1, cV);
            cV = fmaf(wv4.z, y2, cV); cV = fmaf(wv4.w, y3, cV);
        }
        sK[j * SP + 64] = cK; sK[j * SP + 65] = 0.f; sK[j * SP + 66] = 0.f; sK[j * SP + 67] = 0.f;
        sQ[j * SP + 64] = cQ; sQ[j * SP + 65] = 0.f; sQ[j * SP + 66] = 0.f; sQ[j * SP + 67] = 0.f;
        sV[j * SP + 64] = cV; sV[j * SP + 65] = 0.f; sV[j * SP + 66] = 0.f; sV[j * SP + 67] = 0.f;
    }
}

// Fused 2-matrix projection (layer-2 q2 for both heads in one Y2 sweep)
__device__ __forceinline__ void gemm_KQ2(
    const float* __restrict__ Wa, const float* __restrict__ Wb,
    const float* __restrict__ sY,
    float* __restrict__ sA, float* __restrict__ sB2) {
    {
        int tid = threadIdx.x;
        int j0 = (tid >> 4) << 2;
        int t0 = (tid & 15) << 2;
        u64 aA[4][2], aB[4][2];
        #pragma unroll
        for (int r = 0; r < 4; r++) {
            aA[r][0] = aA[r][1] = 0ull;
            aB[r][0] = aB[r][1] = 0ull;
        }
        #pragma unroll 1
        for (int k = 0; k < HH; k += 4) {
            ulonglong2 b0 = *(const ulonglong2*)(sY + (k + 0) * SP + t0);
            ulonglong2 b1 = *(const ulonglong2*)(sY + (k + 1) * SP + t0);
            ulonglong2 b2 = *(const ulonglong2*)(sY + (k + 2) * SP + t0);
            ulonglong2 b3 = *(const ulonglong2*)(sY + (k + 3) * SP + t0);
            #pragma unroll
            for (int r = 0; r < 4; r++) {
                float4 wa = *(const float4*)(Wa + (j0 + r) * HH + k);
                ACC_MAT(wa, b0, b1, b2, b3, aA[r]);
                float4 wb = *(const float4*)(Wb + (j0 + r) * HH + k);
                ACC_MAT(wb, b0, b1, b2, b3, aB[r]);
            }
        }
        #pragma unroll
        for (int r = 0; r < 4; r++) {
            ulonglong2 o;
            o.x = aA[r][0]; o.y = aA[r][1]; *(ulonglong2*)(sA  + (j0 + r) * SP + t0) = o;
            o.x = aB[r][0]; o.y = aB[r][1]; *(ulonglong2*)(sB2 + (j0 + r) * SP + t0) = o;
        }
    }
    if (threadIdx.x < HH) {
        int j = threadIdx.x;
        float cA = 0.f, cB = 0.f;
        #pragma unroll 4
        for (int k = 0; k < HH; k += 4) {
            float y0 = sY[(k + 0) * SP + 64];
            float y1 = sY[(k + 1) * SP + 64];
            float y2 = sY[(k + 2) * SP + 64];
            float y3 = sY[(k + 3) * SP + 64];
            float4 wa4 = *(const float4*)(Wa + j * HH + k);
            cA = fmaf(wa4.x, y0, cA); cA = fmaf(wa4.y, y1, cA);
            cA = fmaf(wa4.z, y2, cA); cA = fmaf(wa4.w, y3, cA);
            float4 wb4 = *(const float4*)(Wb + j * HH + k);
            cB = fmaf(wb4.x, y0, cB); cB = fmaf(wb4.y, y1, cB);
            cB = fmaf(wb4.z, y2, cB); cB = fmaf(wb4.w, y3, cB);
        }
        sA[j * SP + 64]  = cA; sA[j * SP + 65]  = 0.f; sA[j * SP + 66]  = 0.f; sA[j * SP + 67]  = 0.f;
        sB2[j * SP + 64] = cB; sB2[j * SP + 65] = 0.f; sB2[j * SP + 66] = 0.f; sB2[j * SP + 67] = 0.f;
    }
}

// sKQ[s*SP + t] = sum_i sK[i*SP + s] * sQ[i*SP + t]
// Main: 512 tiles of 4s x 2t; a-load is warp-uniform LDS.128 broadcast.
// Tail: row s=64 (t 0..64) and col t=64 (s 0..63).
__device__ __forceinline__ void gemm_kq(const float* __restrict__ sK,
                                        const float* __restrict__ sQ,
                                        float* __restrict__ sKQ) {
    {
        int tid = threadIdx.x;
        int s0 = (tid >> 5) << 2;        // warp-uniform, 0..60
        int t0 = (tid & 31) << 1;        // 0..62
        u64 acc0 = 0ull, acc1 = 0ull, acc2 = 0ull, acc3 = 0ull;
        #pragma unroll 4
        for (int i = 0; i < HH; i++) {
            float4 a = *(const float4*)(sK + i * SP + s0);
            u64 b = *(const u64*)(sQ + i * SP + t0);
            acc0 = fma2(pack2(a.x, a.x), b, acc0);
            acc1 = fma2(pack2(a.y, a.y), b, acc1);
            acc2 = fma2(pack2(a.z, a.z), b, acc2);
            acc3 = fma2(pack2(a.w, a.w), b, acc3);
        }
        *(u64*)(sKQ + (s0 + 0) * SP + t0) = acc0;
        *(u64*)(sKQ + (s0 + 1) * SP + t0) = acc1;
        *(u64*)(sKQ + (s0 + 2) * SP + t0) = acc2;
        *(u64*)(sKQ + (s0 + 3) * SP + t0) = acc3;
    }
    // tail: (s=64, t=0..64) and (s=0..63, t=64)
    if (threadIdx.x < 129) {
        int id = threadIdx.x;
        int s = (id < 65) ? 64 : (id - 65);
        int t = (id < 65) ? id : 64;
        float acc = 0.f;
        #pragma unroll 8
        for (int i = 0; i < HH; i++)
            acc = fmaf(sK[i * SP + s], sQ[i * SP + t], acc);
        sKQ[s * SP + t] = acc;
    }
}

// row-wise softmax over t in [0,65); zeroes pad cols 65..67 and pad rows 65..67
__device__ __forceinline__ void softmax_rows(float* __restrict__ sKQ) {
    int warp = threadIdx.x >> 5, lane = threadIdx.x & 31;
    for (int s = warp; s < SS; s += NT / 32) {
        float* row = sKQ + s * SP;
        float v0 = row[lane], v1 = row[lane + 32], v2 = row[64];
        float m = fmaxf(fmaxf(v0, v1), v2);
        #pragma unroll
        for (int o = 16; o; o >>= 1) m = fmaxf(m, __shfl_xor_sync(0xffffffffu, m, o));
        float e0 = expf(v0 - m), e1 = expf(v1 - m), e2 = expf(v2 - m);
        float sum = e0 + e1;
        #pragma unroll
        for (int o = 16; o; o >>= 1) sum += __shfl_xor_sync(0xffffffffu, sum, o);
        float denom = sum + e2;
        row[lane] = e0 / denom;
        row[lane + 32] = e1 / denom;
        if (lane == 0) { row[64] = e2 / denom; row[65] = 0.f; row[66] = 0.f; row[67] = 0.f; }
    }
    if (threadIdx.x < 3 * SP) sKQ[SS * SP + threadIdx.x] = 0.f;  // zero rows 65..67
}

// sO[s*HH + i] = sum_t sKQ[s*SP + t] * sV[i*SP + t]
// Main: 512 tiles (s<64, warp-uniform s-strip). Tail: row s=64.
__device__ __forceinline__ void gemm_O(const float* __restrict__ sKQ,
                                       const float* __restrict__ sV,
                                       float* __restrict__ sO) {
    {
        int tid = threadIdx.x;
        int s0 = (tid >> 5) << 2;        // 0..60
        int i0 = (tid & 31) << 2;        // 0..124
        float4 acc0 = {0,0,0,0}, acc1 = {0,0,0,0}, acc2 = {0,0,0,0}, acc3 = {0,0,0,0};
        #pragma unroll 4
        for (int t = 0; t < SP; t += 4) {
            float4 p0 = *(const float4*)(sKQ + (s0 + 0) * SP + t);
            float4 p1 = *(const float4*)(sKQ + (s0 + 1) * SP + t);
            float4 p2 = *(const float4*)(sKQ + (s0 + 2) * SP + t);
            float4 p3 = *(const float4*)(sKQ + (s0 + 3) * SP + t);
            float4 v0 = *(const float4*)(sV + (i0 + 0) * SP + t);
            float4 v1 = *(const float4*)(sV + (i0 + 1) * SP + t);
            float4 v2 = *(const float4*)(sV + (i0 + 2) * SP + t);
            float4 v3 = *(const float4*)(sV + (i0 + 3) * SP + t);
            acc0.x = dot4(p0, v0, acc0.x); acc0.y = dot4(p0, v1, acc0.y);
            acc0.z = dot4(p0, v2, acc0.z); acc0.w = dot4(p0, v3, acc0.w);
            acc1.x = dot4(p1, v0, acc1.x); acc1.y = dot4(p1, v1, acc1.y);
            acc1.z = dot4(p1, v2, acc1.z); acc1.w = dot4(p1, v3, acc1.w);
            acc2.x = dot4(p2, v0, acc2.x); acc2.y = dot4(p2, v1, acc2.y);
            acc2.z = dot4(p2, v2, acc2.z); acc2.w = dot4(p2, v3, acc2.w);
            acc3.x = dot4(p3, v0, acc3.x); acc3.y = dot4(p3, v1, acc3.y);
            acc3.z = dot4(p3, v2, acc3.z); acc3.w = dot4(p3, v3, acc3.w);
        }
        *(float4*)(sO + (s0 + 0) * HH + i0) = acc0;
        *(float4*)(sO + (s0 + 1) * HH + i0) = acc1;
        *(float4*)(sO + (s0 + 2) * HH + i0) = acc2;
        *(float4*)(sO + (s0 + 3) * HH + i0) = acc3;
    }
    // tail: s = 64
    if (threadIdx.x < HH) {
        int i = threadIdx.x;
        float acc = 0.f;
        #pragma unroll 4
        for (int t = 0; t < SP; t += 4) {
            float4 p = *(const float4*)(sKQ + 64 * SP + t);
            float4 v = *(const float4*)(sV + i * SP + t);
            acc = dot4(p, v, acc);
        }
        sO[64 * HH + i] = acc;
    }
}

// sZ[s*HH + j] (FIRST: =, else continue chain) sum_i sO[s*HH+i] * L[i*HH+j]
template <int FIRST>
__device__ __forceinline__ void gemm_Z(const float* __restrict__ sO,
                                       const float* __restrict__ L,
                                       float* __restrict__ sZ) {
    {
        int tid = threadIdx.x;
        int s0 = (tid >> 5) << 2;        // 0..60
        int j0 = (tid & 31) << 2;        // 0..124
        u64 acc[4][2];
        #pragma unroll
        for (int r = 0; r < 4; r++) {
            if (FIRST) { acc[r][0] = 0ull; acc[r][1] = 0ull; }
            else {
                ulonglong2 z = *(const ulonglong2*)(sZ + (s0 + r) * HH + j0);
                acc[r][0] = z.x; acc[r][1] = z.y;
            }
        }
        #pragma unroll 2
        for (int i = 0; i < HH; i += 4) {
            ulonglong2 l0 = *(const ulonglong2*)(L + (i + 0) * HH + j0);
            ulonglong2 l1 = *(const ulonglong2*)(L + (i + 1) * HH + j0);
            ulonglong2 l2 = *(const ulonglong2*)(L + (i + 2) * HH + j0);
            ulonglong2 l3 = *(const ulonglong2*)(L + (i + 3) * HH + j0);
            #pragma unroll
            for (int r = 0; r < 4; r++) {
                float4 o = *(const float4*)(sO + (s0 + r) * HH + i);
                ACC_MAT(o, l0, l1, l2, l3, acc[r]);
            }
        }
        #pragma unroll
        for (int r = 0; r < 4; r++) {
            ulonglong2 o; o.x = acc[r][0]; o.y = acc[r][1];
            *(ulonglong2*)(sZ + (s0 + r) * HH + j0) = o;
        }
    }
    // tail: s = 64
    if (threadIdx.x < HH) {
        int j = threadIdx.x;
        float acc = FIRST ? 0.f : sZ[64 * HH + j];
        #pragma unroll 8
        for (int i = 0; i < HH; i++)
            acc = fmaf(sO[64 * HH + i], L[i * HH + j], acc);
        sZ[64 * HH + j] = acc;
    }
}

// smem layout (floats): 5 big buffers P0..P4 of 8704 + KQ + EX
//  P0 @     0 : Y (layer1), then Z (stride 128)
//  P1 @  8704 : K0 -> O0 -> q2a
//  P2 @ 17408 : Q0 -> K1 -> O1 -> q2b
//  P3 @ 26112 : V0 -> Q1 -> Y2
//  P4 @ 34816 : V1
//  KQ @ 43520 : 4624
//  EX @ 48144 : 1024
#define SMEM_FLOATS 49168

__global__ void __launch_bounds__(NT, 1) board_kernel(
    const float* __restrict__ inp, const float* __restrict__ emb,
    const float* __restrict__ wk11, const float* __restrict__ wq11, const float* __restrict__ wv11,
    const float* __restrict__ wk12, const float* __restrict__ wq12, const float* __restrict__ wv12,
    const float* __restrict__ L1,
    const float* __restrict__ wk21, const float* __restrict__ wq21, const float* __restrict__ wv21,
    const float* __restrict__ wk22, const float* __restrict__ wq22, const float* __restrict__ wv22,
    const float* __restrict__ L2, const float* __restrict__ L3, const float* __restrict__ L4,
    float* __restrict__ out) {
    extern __shared__ float sm[];
    float* P0  = sm;
    float* P1  = sm + 8704;
    float* P2  = sm + 17408;
    float* P3  = sm + 26112;
    float* P4  = sm + 34816;
    float* sKQ = sm + 43520;
    float* sEX = sm + 48144;

    float* sc   = sEX;          // 128 (layer-2 c = Wk2 @ y64)
    float* sw   = sEX + 128;    // 72 (softmax row)
    float* syw  = sEX + 200;    // 128
    float* satt = sEX + 328;    // 256
    float* sh2  = sEX + 584;    // 128
    float* sh3  = sEX + 712;    // 64

    const int b = blockIdx.x;
    const int tid = threadIdx.x;
    const float* x = inp + (size_t)b * 64;

    // Y[j][s] = emb[j][s] * x[s], x[64]=1; padding cols zero.
    for (int idx = tid; idx < HH * SP; idx += NT) {
        int j = idx / SP, s = idx - j * SP;
        float v = 0.f;
        if (s < 64)       v = emb[j * 65 + s] * x[s];
        else if (s == 64) v = emb[j * 65 + 64];
        P0[idx] = v;
    }
    __syncthreads();

    // ---- layer 1, head 0 ----
    gemm_KQV(wk11, wq11, wv11, P0, P1, P2, P3);   // K0, Q0, V0 in one Y sweep
    __syncthreads();
    gemm_kq(P1, P2, sKQ);                         // KQ = K0^T @ Q0
    __syncthreads();
    softmax_rows(sKQ);
    __syncthreads();
    gemm_O(sKQ, P3, P1);                          // O0 = SM @ V0^T (over K0)
    __syncthreads();

    // ---- layer 1, head 1 ----
    gemm_KQV(wk12, wq12, wv12, P0, P2, P3, P4);   // K1, Q1, V1 (over Q0, V0)
    __syncthreads();
    gemm_kq(P2, P3, sKQ);
    __syncthreads();
    softmax_rows(sKQ);
    __syncthreads();
    gemm_O(sKQ, P4, P2);                          // O1 (over K1)
    __syncthreads();

    // Z = O0 @ L1[:128] then += O1 @ L1[128:], single 256-deep in-order chain.
    // Y (P0) is dead now; Z lives in P0 with stride 128.
    gemm_Z<1>(P1, L1,           P0);
    __syncthreads();
    gemm_Z<0>(P2, L1 + HH * HH, P0);
    __syncthreads();

    // tanh + transpose: Y2[j][s] = tanh(Z[s][j])  -> P3
    for (int idx = tid; idx < HH * SP; idx += NT) {
        int j = idx / SP, s = idx - j * SP;
        P3[idx] = (s < SS) ? tanhf(P0[s * HH + j]) : 0.f;
    }
    __syncthreads();

    // ---- layer 2: q2 for BOTH heads in one Y2 sweep ----
    gemm_KQ2(wq21, wq22, P3, P1, P2);             // q2a -> P1, q2b -> P2
    __syncthreads();

    int lane = tid & 31;
    #pragma unroll 1
    for (int a2 = 0; a2 < 2; a2++) {
        const float* Wk = (a2 == 0) ? wk21 : wk22;
        const float* Wv = (a2 == 0) ? wv21 : wv22;
        const float* q2 = (a2 == 0) ? P1 : P2;
        if (tid < HH) {                       // c[i] = sum_j Wk[i][j] * y64[j]  (in-order)
            float acc = 0.f;
            #pragma unroll 8
            for (int j = 0; j < HH; j++)
                acc = fmaf(Wk[tid * HH + j], P3[j * SP + 64], acc);
            sc[tid] = acc;
        }
        __syncthreads();
        if (tid < SS) {                       // logits[t] = sum_i c[i] * q2[i][t]  (in-order)
            float acc = 0.f;
            #pragma unroll 8
            for (int i = 0; i < HH; i++)
                acc = fmaf(sc[i], q2[i * SP + tid], acc);
            sw[tid] = acc;
        }
        __syncthreads();
        if (tid < 32) {                       // softmax (single row)
            float v0 = sw[lane], v1 = sw[lane + 32], v2 = sw[64];
            float m = fmaxf(fmaxf(v0, v1), v2);
            #pragma unroll
            for (int o = 16; o; o >>= 1) m = fmaxf(m, __shfl_xor_sync(0xffffffffu, m, o));
            float e0 = expf(v0 - m), e1 = expf(v1 - m), e2 = expf(v2 - m);
            float sum = e0 + e1;
            #pragma unroll
            for (int o = 16; o; o >>= 1) sum += __shfl_xor_sync(0xffffffffu, sum, o);
            float denom = sum + e2;
            sw[lane] = e0 / denom;
            sw[lane + 32] = e1 / denom;
            if (lane == 0) { sw[64] = e2 / denom; sw[65] = 0.f; sw[66] = 0.f; sw[67] = 0.f; }
        }
        __syncthreads();
        if (tid < HH) {                       // yw[j] = sum_t w[t] * Y2[j][t]
            float acc = 0.f;
            #pragma unroll
            for (int t = 0; t < SP; t += 4) {
                float4 y4 = *(const float4*)(P3 + tid * SP + t);
                float4 w4 = *(const float4*)(sw + t);
                acc = dot4(y4, w4, acc);
            }
            syw[tid] = acc;
        }
        __syncthreads();
        if (tid < HH) {                       // att64[i] = sum_j Wv[i][j] * yw[j]
            float acc = 0.f;
            #pragma unroll 8
            for (int j = 0; j < HH; j += 4) {
                float4 w4 = *(const float4*)(Wv + tid * HH + j);
                float4 y4 = *(const float4*)(syw + j);
                acc = dot4(w4, y4, acc);
            }
            satt[a2 * HH + tid] = acc;
        }
        __syncthreads();
    }

    // head: h2 = tanh(cat(att) @ L2), h3 = tanh(h2 @ L3), score = h3 @ L4
    if (tid < HH) {
        float acc = 0.f;
        #pragma unroll 8
        for (int i = 0; i < 2 * HH; i++)
            acc = fmaf(satt[i], L2[i * HH + tid], acc);
        sh2[tid] = tanhf(acc);
    }
    __syncthreads();
    if (tid < 64) {
        float acc = 0.f;
        #pragma unroll 8
        for (int j = 0; j < HH; j++)
            acc = fmaf(sh2[j], L3[j * 64 + tid], acc);
        sh3[tid] = tanhf(acc);
    }
    __syncthreads();
    if (tid == 0) {
        float acc = 0.f;
        #pragma unroll
        for (int m = 0; m < 64; m++) acc = fmaf(sh3[m], L4[m], acc);
        out[b] = acc;
    }
}

extern "C" void kernel_launch(void* const* d_in, const int* in_sizes, int n_in,
                              void* d_out, int out_size) {
    const float* inputs = (const float*)d_in[0];
    const float* emb    = (const float*)d_in[1];
    const float* wk11   = (const float*)d_in[2];
    const float* wq11   = (const float*)d_in[3];
    const float* wv11   = (const float*)d_in[4];
    const float* wk12   = (const float*)d_in[5];
    const float* wq12   = (const float*)d_in[6];
    const float* wv12   = (const float*)d_in[7];
    const float* L1     = (const float*)d_in[8];
    const float* wk21   = (const float*)d_in[9];
    const float* wq21   = (const float*)d_in[10];
    const float* wv21   = (const float*)d_in[11];
    const float* wk22   = (const float*)d_in[12];
    const float* wq22   = (const float*)d_in[13];
    const float* wv22   = (const float*)d_in[14];
    const float* L2     = (const float*)d_in[15];
    const float* L3     = (const float*)d_in[16];
    const float* L4     = (const float*)d_in[17];
    (void)n_in; (void)in_sizes;

    int B = out_size;  // one score per board (8192)

    size_t smem = SMEM_FLOATS * sizeof(float);
    cudaFuncSetAttribute(board_kernel, cudaFuncAttributeMaxDynamicSharedMemorySize, (int)smem);

    board_kernel<<<B, NT, smem>>>(inputs, emb,
                                  wk11, wq11, wv11, wk12, wq12, wv12, L1,
                                  wk21, wq21, wv21, wk22, wq22, wv22, L2, L3, L4,
                                  (float*)d_out);
}

// round 8
// speedup vs baseline: 1.4078x; 1.0238x over previous
#include <cuda_runtime.h>
#include <math.h>

#define HH 128
#define SS 65
#define SP 68          // padded S stride (cols 65..67 zero where read)
#define VTS 132        // transposed-V stride (bank-spread, 16B-aligned rows)
#define NT 512

typedef unsigned long long u64;

__device__ __forceinline__ u64 pack2(float lo, float hi) {
    u64 r; asm("mov.b64 %0, {%1, %2};" : "=l"(r) : "f"(lo), "f"(hi)); return r;
}
__device__ __forceinline__ float2 unpack2(u64 p) {
    float2 v; asm("mov.b64 {%0, %1}, %2;" : "=f"(v.x), "=f"(v.y) : "l"(p)); return v;
}
__device__ __forceinline__ u64 fma2(u64 a, u64 b, u64 c) {
    u64 d; asm("fma.rn.f32x2 %0, %1, %2, %3;" : "=l"(d) : "l"(a), "l"(b), "l"(c)); return d;
}
__device__ __forceinline__ float dot4(const float4& a, const float4& b, float acc) {
    acc = fmaf(a.x, b.x, acc);
    acc = fmaf(a.y, b.y, acc);
    acc = fmaf(a.z, b.z, acc);
    acc = fmaf(a.w, b.w, acc);
    return acc;
}

#define PF_L1(p) asm volatile("prefetch.global.L1 [%0];" :: "l"(p))

#define ACC_MAT(AR, Bx, By, Bz, Bw, ACC)                                              \
    do {                                                                              \
        u64 p_;                                                                       \
        p_ = pack2(AR.x, AR.x); ACC[0] = fma2(p_, Bx.x, ACC[0]); ACC[1] = fma2(p_, Bx.y, ACC[1]); \
        p_ = pack2(AR.y, AR.y); ACC[0] = fma2(p_, By.x, ACC[0]); ACC[1] = fma2(p_, By.y, ACC[1]); \
        p_ = pack2(AR.z, AR.z); ACC[0] = fma2(p_, Bz.x, ACC[0]); ACC[1] = fma2(p_, Bz.y, ACC[1]); \
        p_ = pack2(AR.w, AR.w); ACC[0] = fma2(p_, Bw.x, ACC[0]); ACC[1] = fma2(p_, Bw.y, ACC[1]); \
    } while (0)

// Fused K/Q/V projection, one Y sweep. K,Q stored [j][t] stride SP; V stored
// TRANSPOSED [t][j] stride VTS (pad rows 65..67 zeroed). Chains: k ascending.
__device__ __forceinline__ void gemm_KQV(
    const float* __restrict__ Wk, const float* __restrict__ Wq, const float* __restrict__ Wv,
    const float* __restrict__ sY,
    float* __restrict__ sK, float* __restrict__ sQ, float* __restrict__ sVt) {
    {
        int tid = threadIdx.x;
        int j0 = (tid >> 4) << 2;        // 0..124
        int t0 = (tid & 15) << 2;        // 0..60
        u64 aK[4][2], aQ[4][2], aV[4][2];
        #pragma unroll
        for (int r = 0; r < 4; r++) {
            aK[r][0] = aK[r][1] = 0ull;
            aQ[r][0] = aQ[r][1] = 0ull;
            aV[r][0] = aV[r][1] = 0ull;
        }
        #pragma unroll 1
        for (int kb = 0; kb < HH; kb += 32) {
            if (kb + 32 < HH) {
                #pragma unroll
                for (int r = 0; r < 4; r++) {
                    PF_L1(Wk + (j0 + r) * HH + kb + 32);
                    PF_L1(Wq + (j0 + r) * HH + kb + 32);
                    PF_L1(Wv + (j0 + r) * HH + kb + 32);
                }
            }
            #pragma unroll 1
            for (int k = kb; k < kb + 32; k += 4) {
                ulonglong2 b0 = *(const ulonglong2*)(sY + (k + 0) * SP + t0);
                ulonglong2 b1 = *(const ulonglong2*)(sY + (k + 1) * SP + t0);
                ulonglong2 b2 = *(const ulonglong2*)(sY + (k + 2) * SP + t0);
                ulonglong2 b3 = *(const ulonglong2*)(sY + (k + 3) * SP + t0);
                #pragma unroll
                for (int r = 0; r < 4; r++) {
                    float4 ak = *(const float4*)(Wk + (j0 + r) * HH + k);
                    ACC_MAT(ak, b0, b1, b2, b3, aK[r]);
                    float4 aq = *(const float4*)(Wq + (j0 + r) * HH + k);
                    ACC_MAT(aq, b0, b1, b2, b3, aQ[r]);
                    float4 av = *(const float4*)(Wv + (j0 + r) * HH + k);
                    ACC_MAT(av, b0, b1, b2, b3, aV[r]);
                }
            }
        }
        #pragma unroll
        for (int r = 0; r < 4; r++) {
            ulonglong2 o;
            o.x = aK[r][0]; o.y = aK[r][1]; *(ulonglong2*)(sK + (j0 + r) * SP + t0) = o;
            o.x = aQ[r][0]; o.y = aQ[r][1]; *(ulonglong2*)(sQ + (j0 + r) * SP + t0) = o;
        }
        // V transposed store
        float av4[4][4];
        #pragma unroll
        for (int r = 0; r < 4; r++) {
            float2 lo = unpack2(aV[r][0]), hi = unpack2(aV[r][1]);
            av4[r][0] = lo.x; av4[r][1] = lo.y; av4[r][2] = hi.x; av4[r][3] = hi.y;
        }
        #pragma unroll
        for (int tt = 0; tt < 4; tt++) {
            float4 c; c.x = av4[0][tt]; c.y = av4[1][tt]; c.z = av4[2][tt]; c.w = av4[3][tt];
            *(float4*)(sVt + (t0 + tt) * VTS + j0) = c;
        }
    }
    // tail: t = 64; Vt pad rows zeroed
    if (threadIdx.x < HH) {
        int j = threadIdx.x;
        float cK = 0.f, cQ = 0.f, cV = 0.f;
        #pragma unroll 4
        for (int k = 0; k < HH; k += 4) {
            float y0 = sY[(k + 0) * SP + 64];
            float y1 = sY[(k + 1) * SP + 64];
            float y2 = sY[(k + 2) * SP + 64];
            float y3 = sY[(k + 3) * SP + 64];
            float4 wk4 = *(const float4*)(Wk + j * HH + k);
            cK = fmaf(wk4.x, y0, cK); cK = fmaf(wk4.y, y1, cK);
            cK = fmaf(wk4.z, y2, cK); cK = fmaf(wk4.w, y3, cK);
            float4 wq4 = *(const float4*)(Wq + j * HH + k);
            cQ = fmaf(wq4.x, y0, cQ); cQ = fmaf(wq4.y, y1, cQ);
            cQ = fmaf(wq4.z, y2, cQ); cQ = fmaf(wq4.w, y3, cQ);
            float4 wv4 = *(const float4*)(Wv + j * HH + k);
            cV = fmaf(wv4.x, y0, cV); cV = fmaf(wv4.y, y1, cV);
            cV = fmaf(wv4.z, y2, cV); cV = fmaf(wv4.w, y3, cV);
        }
        sK[j * SP + 64] = cK;
        sQ[j * SP + 64] = cQ;
        sVt[64 * VTS + j] = cV;
        sVt[65 * VTS + j] = 0.f;
        sVt[66 * VTS + j] = 0.f;
        sVt[67 * VTS + j] = 0.f;
    }
}

// Fused 2-matrix projection (layer-2 q2 both heads), stride SP outputs.
__device__ __forceinline__ void gemm_KQ2(
    const float* __restrict__ Wa, const float* __restrict__ Wb,
    const float* __restrict__ sY,
    float* __restrict__ sA, float* __restrict__ sB2) {
    {
        int tid = threadIdx.x;
        int j0 = (tid >> 4) << 2;
        int t0 = (tid & 15) << 2;
        u64 aA[4][2], aB[4][2];
        #pragma unroll
        for (int r = 0; r < 4; r++) {
            aA[r][0] = aA[r][1] = 0ull;
            aB[r][0] = aB[r][1] = 0ull;
        }
        #pragma unroll 1
        for (int kb = 0; kb < HH; kb += 32) {
            if (kb + 32 < HH) {
                #pragma unroll
                for (int r = 0; r < 4; r++) {
                    PF_L1(Wa + (j0 + r) * HH + kb + 32);
                    PF_L1(Wb + (j0 + r) * HH + kb + 32);
                }
            }
            #pragma unroll 1
            for (int k = kb; k < kb + 32; k += 4) {
                ulonglong2 b0 = *(const ulonglong2*)(sY + (k + 0) * SP + t0);
                ulonglong2 b1 = *(const ulonglong2*)(sY + (k + 1) * SP + t0);
                ulonglong2 b2 = *(const ulonglong2*)(sY + (k + 2) * SP + t0);
                ulonglong2 b3 = *(const ulonglong2*)(sY + (k + 3) * SP + t0);
                #pragma unroll
                for (int r = 0; r < 4; r++) {
                    float4 wa = *(const float4*)(Wa + (j0 + r) * HH + k);
                    ACC_MAT(wa, b0, b1, b2, b3, aA[r]);
                    float4 wb = *(const float4*)(Wb + (j0 + r) * HH + k);
                    ACC_MAT(wb, b0, b1, b2, b3, aB[r]);
                }
            }
        }
        #pragma unroll
        for (int r = 0; r < 4; r++) {
            ulonglong2 o;
            o.x = aA[r][0]; o.y = aA[r][1]; *(ulonglong2*)(sA  + (j0 + r) * SP + t0) = o;
            o.x = aB[r][0]; o.y = aB[r][1]; *(ulonglong2*)(sB2 + (j0 + r) * SP + t0) = o;
        }
    }
    if (threadIdx.x < HH) {
        int j = threadIdx.x;
        float cA = 0.f, cB = 0.f;
        #pragma unroll 4
        for (int k = 0; k < HH; k += 4) {
            float y0 = sY[(k + 0) * SP + 64];
            float y1 = sY[(k + 1) * SP + 64];
            float y2 = sY[(k + 2) * SP + 64];
            float y3 = sY[(k + 3) * SP + 64];
            float4 wa4 = *(const float4*)(Wa + j * HH + k);
            cA = fmaf(wa4.x, y0, cA); cA = fmaf(wa4.y, y1, cA);
            cA = fmaf(wa4.z, y2, cA); cA = fmaf(wa4.w, y3, cA);
            float4 wb4 = *(const float4*)(Wb + j * HH + k);
            cB = fmaf(wb4.x, y0, cB); cB = fmaf(wb4.y, y1, cB);
            cB = fmaf(wb4.z, y2, cB); cB = fmaf(wb4.w, y3, cB);
        }
        sA[j * SP + 64]  = cA;
        sB2[j * SP + 64] = cB;
    }
}

// Row-wise softmax on one row (65 real cols), warp-collective. Zeroes pads.
__device__ __forceinline__ void softmax_row(float* __restrict__ row, int lane) {
    float v0 = row[lane], v1 = row[lane + 32], v2 = row[64];
    float m = fmaxf(fmaxf(v0, v1), v2);
    #pragma unroll
    for (int o = 16; o; o >>= 1) m = fmaxf(m, __shfl_xor_sync(0xffffffffu, m, o));
    float e0 = expf(v0 - m), e1 = expf(v1 - m), e2 = expf(v2 - m);
    float sum = e0 + e1;
    #pragma unroll
    for (int o = 16; o; o >>= 1) sum += __shfl_xor_sync(0xffffffffu, sum, o);
    float denom = sum + e2;
    row[lane] = e0 / denom;
    row[lane + 32] = e1 / denom;
    if (lane == 0) { row[64] = e2 / denom; row[65] = 0.f; row[66] = 0.f; row[67] = 0.f; }
}

// Fused kq -> softmax -> O, barrier-free (warp row-ownership).
// warp w owns rows 4w..4w+3; warp 0 additionally owns row 64 end-to-end.
// O[s*HH+i] = sum_t SM[s][t] * Vt[t][i], chain t ascending.
__device__ __forceinline__ void attn_fused(const float* __restrict__ sK,
                                           const float* __restrict__ sQ,
                                           const float* __restrict__ sVt,
                                           float* __restrict__ sKQ,
                                           float* __restrict__ sO) {
    int tid = threadIdx.x, w = tid >> 5, lane = tid & 31;
    int s0 = w << 2, t2 = lane << 1;

    // ---- kq main: rows s0..s0+3, cols t2, t2+1 (chain i ascending)
    {
        u64 a0 = 0ull, a1 = 0ull, a2 = 0ull, a3 = 0ull;
        #pragma unroll 4
        for (int i = 0; i < HH; i++) {
            float4 kv = *(const float4*)(sK + i * SP + s0);
            u64 q = *(const u64*)(sQ + i * SP + t2);
            a0 = fma2(pack2(kv.x, kv.x), q, a0);
            a1 = fma2(pack2(kv.y, kv.y), q, a1);
            a2 = fma2(pack2(kv.z, kv.z), q, a2);
            a3 = fma2(pack2(kv.w, kv.w), q, a3);
        }
        *(u64*)(sKQ + (s0 + 0) * SP + t2) = a0;
        *(u64*)(sKQ + (s0 + 1) * SP + t2) = a1;
        *(u64*)(sKQ + (s0 + 2) * SP + t2) = a2;
        *(u64*)(sKQ + (s0 + 3) * SP + t2) = a3;
    }
    // col 64 for own rows (lanes 0..3, scalar in-order)
    if (lane < 4) {
        int s = s0 + lane;
        float acc = 0.f;
        #pragma unroll 8
        for (int i = 0; i < HH; i++)
            acc = fmaf(sK[i * SP + s], sQ[i * SP + 64], acc);
        sKQ[s * SP + 64] = acc;
    }
    // row 64 (warp 0): packed pairs per lane + corner by lane 0
    if (w == 0) {
        u64 acc = 0ull;
        #pragma unroll 8
        for (int i = 0; i < HH; i++) {
            float kk = sK[i * SP + 64];
            acc = fma2(pack2(kk, kk), *(const u64*)(sQ + i * SP + t2), acc);
        }
        *(u64*)(sKQ + 64 * SP + t2) = acc;
        if (lane == 0) {
            float a = 0.f;
            #pragma unroll 8
            for (int i = 0; i < HH; i++)
                a = fmaf(sK[i * SP + 64], sQ[i * SP + 64], a);
            sKQ[64 * SP + 64] = a;
        }
    }
    __syncwarp();

    // ---- softmax on own rows
    #pragma unroll
    for (int r = 0; r < 4; r++) softmax_row(sKQ + (s0 + r) * SP, lane);
    if (w == 0) softmax_row(sKQ + 64 * SP, lane);
    __syncwarp();

    // ---- O: rows s0..s0+3, i0 = lane*4, packed over i-pairs, chain t ascending
    {
        int i0 = lane << 2;
        u64 o[4][2];
        #pragma unroll
        for (int r = 0; r < 4; r++) { o[r][0] = 0ull; o[r][1] = 0ull; }
        #pragma unroll 1
        for (int tb = 0; tb < SP; tb += 4) {
            float4 q0 = *(const float4*)(sKQ + (s0 + 0) * SP + tb);
            float4 q1 = *(const float4*)(sKQ + (s0 + 1) * SP + tb);
            float4 q2v = *(const float4*)(sKQ + (s0 + 2) * SP + tb);
            float4 q3 = *(const float4*)(sKQ + (s0 + 3) * SP + tb);
            float p0[4] = {q0.x, q0.y, q0.z, q0.w};
            float p1[4] = {q1.x, q1.y, q1.z, q1.w};
            float p2[4] = {q2v.x, q2v.y, q2v.z, q2v.w};
            float p3[4] = {q3.x, q3.y, q3.z, q3.w};
            #pragma unroll
            for (int tt = 0; tt < 4; tt++) {
                ulonglong2 vv = *(const ulonglong2*)(sVt + (tb + tt) * VTS + i0);
                u64 pp;
                pp = pack2(p0[tt], p0[tt]); o[0][0] = fma2(pp, vv.x, o[0][0]); o[0][1] = fma2(pp, vv.y, o[0][1]);
                pp = pack2(p1[tt], p1[tt]); o[1][0] = fma2(pp, vv.x, o[1][0]); o[1][1] = fma2(pp, vv.y, o[1][1]);
                pp = pack2(p2[tt], p2[tt]); o[2][0] = fma2(pp, vv.x, o[2][0]); o[2][1] = fma2(pp, vv.y, o[2][1]);
                pp = pack2(p3[tt], p3[tt]); o[3][0] = fma2(pp, vv.x, o[3][0]); o[3][1] = fma2(pp, vv.y, o[3][1]);
            }
        }
        #pragma unroll
        for (int r = 0; r < 4; r++) {
            ulonglong2 ov; ov.x = o[r][0]; ov.y = o[r][1];
            *(ulonglong2*)(sO + (s0 + r) * HH + i0) = ov;
        }
        // row 64 (warp 0)
        if (w == 0) {
            u64 oa = 0ull, ob = 0ull;
            #pragma unroll 1
            for (int tb = 0; tb < SP; tb += 4) {
                float4 q = *(const float4*)(sKQ + 64 * SP + tb);
                float pr[4] = {q.x, q.y, q.z, q.w};
                #pragma unroll
                for (int tt = 0; tt < 4; tt++) {
                    ulonglong2 vv = *(const ulonglong2*)(sVt + (tb + tt) * VTS + i0);
                    u64 pp = pack2(pr[tt], pr[tt]);
                    oa = fma2(pp, vv.x, oa);
                    ob = fma2(pp, vv.y, ob);
                }
            }
            ulonglong2 ov; ov.x = oa; ov.y = ob;
            *(ulonglong2*)(sO + 64 * HH + i0) = ov;
        }
    }
}

// sZ[s*HH + j] (FIRST: =, else continue chain) sum_i sO[s*HH+i] * L[i*HH+j]
template <int FIRST>
__device__ __forceinline__ void gemm_Z(const float* __restrict__ sO,
                                       const float* __restrict__ L,
                                       float* __restrict__ sZ) {
    {
        int tid = threadIdx.x;
        int s0 = (tid >> 5) << 2;        // 0..60
        int j0 = (tid & 31) << 2;        // 0..124
        u64 acc[4][2];
        #pragma unroll
        for (int r = 0; r < 4; r++) {
            if (FIRST) { acc[r][0] = 0ull; acc[r][1] = 0ull; }
            else {
                ulonglong2 z = *(const ulonglong2*)(sZ + (s0 + r) * HH + j0);
                acc[r][0] = z.x; acc[r][1] = z.y;
            }
        }
        #pragma unroll 1
        for (int i = 0; i < HH; i += 4) {
            if (i + 16 < HH) {
                PF_L1(L + (i + 16) * HH + j0);
                PF_L1(L + (i + 17) * HH + j0);
                PF_L1(L + (i + 18) * HH + j0);
                PF_L1(L + (i + 19) * HH + j0);
            }
            ulonglong2 l0 = *(const ulonglong2*)(L + (i + 0) * HH + j0);
            ulonglong2 l1 = *(const ulonglong2*)(L + (i + 1) * HH + j0);
            ulonglong2 l2 = *(const ulonglong2*)(L + (i + 2) * HH + j0);
            ulonglong2 l3 = *(const ulonglong2*)(L + (i + 3) * HH + j0);
            #pragma unroll
            for (int r = 0; r < 4; r++) {
                float4 o = *(const float4*)(sO + (s0 + r) * HH + i);
                ACC_MAT(o, l0, l1, l2, l3, acc[r]);
            }
        }
        #pragma unroll
        for (int r = 0; r < 4; r++) {
            ulonglong2 o; o.x = acc[r][0]; o.y = acc[r][1];
            *(ulonglong2*)(sZ + (s0 + r) * HH + j0) = o;
        }
    }
    // tail: s = 64 (same tid -> same element across FIRST/continue, no sync needed)
    if (threadIdx.x < HH) {
        int j = threadIdx.x;
        float acc = FIRST ? 0.f : sZ[64 * HH + j];
        #pragma unroll 8
        for (int i = 0; i < HH; i++)
            acc = fmaf(sO[64 * HH + i], L[i * HH + j], acc);
        sZ[64 * HH + j] = acc;
    }
}

// smem layout (floats):
//  P0 @     0 : 8704  Y -> O1 (stride 128)
//  P1 @  8704 : 8704  K0 -> K1 -> Z (stride 128)
//  P2 @ 17408 : 8704  Q0 -> Q1 -> Y2
//  P3 @ 26112 : 8976  V0t -> V1t -> q2a (stride SP fits)
//  P4 @ 35088 : 8704  O0 -> q2b
//  KQ @ 43792 : 4624
//  EX @ 48416 : 1120
#define SMEM_FLOATS 49536

__global__ void __launch_bounds__(NT, 1) board_kernel(
    const float* __restrict__ inp, const float* __restrict__ emb,
    const float* __restrict__ wk11, const float* __restrict__ wq11, const float* __restrict__ wv11,
    const float* __restrict__ wk12, const float* __restrict__ wq12, const float* __restrict__ wv12,
    const float* __restrict__ L1,
    const float* __restrict__ wk21, const float* __restrict__ wq21, const float* __restrict__ wv21,
    const float* __restrict__ wk22, const float* __restrict__ wq22, const float* __restrict__ wv22,
    const float* __restrict__ L2, const float* __restrict__ L3, const float* __restrict__ L4,
    float* __restrict__ out) {
    extern __shared__ float sm[];
    float* P0  = sm;
    float* P1  = sm + 8704;
    float* P2  = sm + 17408;
    float* P3  = sm + 26112;
    float* P4  = sm + 35088;
    float* sKQ = sm + 43792;
    float* sEX = sm + 48416;

    float* sc   = sEX;          // 2 x 128
    float* sw   = sEX + 256;    // 2 x 72 (stride 72)
    float* syw  = sEX + 416;    // 2 x 128
    float* satt = sEX + 672;    // 256
    float* sh2  = sEX + 928;    // 128
    float* sh3  = sEX + 1056;   // 64

    const int b = blockIdx.x;
    const int tid = threadIdx.x;
    const float* x = inp + (size_t)b * 64;

    // Y[j][s] = emb[j][s] * x[s], x[64]=1; padding cols zero.
    for (int idx = tid; idx < HH * SP; idx += NT) {
        int j = idx / SP, s = idx - j * SP;
        float v = 0.f;
        if (s < 64)       v = emb[j * 65 + s] * x[s];
        else if (s == 64) v = emb[j * 65 + 64];
        P0[idx] = v;
    }
    __syncthreads();

    // ---- layer 1, head 0 ----
    gemm_KQV(wk11, wq11, wv11, P0, P1, P2, P3);   // K0, Q0, V0t
    __syncthreads();
    attn_fused(P1, P2, P3, sKQ, P4);              // O0 -> P4
    __syncthreads();

    // ---- layer 1, head 1 ----
    gemm_KQV(wk12, wq12, wv12, P0, P1, P2, P3);   // K1, Q1, V1t
    __syncthreads();
    attn_fused(P1, P2, P3, sKQ, P0);              // O1 -> P0 (Y dead)
    __syncthreads();

    // Z = O0 @ L1[:128] then += O1 @ L1[128:] (single 256-deep in-order chain)
    gemm_Z<1>(P4, L1,           P1);
    gemm_Z<0>(P0, L1 + HH * HH, P1);              // row-ownership identical: no sync
    __syncthreads();

    // tanh + transpose: Y2[j][s] = tanh(Z[s][j]) -> P2
    for (int idx = tid; idx < HH * SP; idx += NT) {
        int j = idx / SP, s = idx - j * SP;
        P2[idx] = (s < SS) ? tanhf(P1[s * HH + j]) : 0.f;
    }
    __syncthreads();

    // ---- layer 2: both heads merged ----
    // c[h][i] = sum_j Wk2h[i][j] * y64[j]  (in-order), concurrent with nothing else
    if (tid < 2 * HH) {
        int h = tid >> 7, i = tid & 127;
        const float* Wk = h ? wk22 : wk21;
        float acc = 0.f;
        #pragma unroll 8
        for (int j = 0; j < HH; j++)
            acc = fmaf(Wk[i * HH + j], P2[j * SP + 64], acc);
        sc[(h << 7) + i] = acc;
    }
    gemm_KQ2(wq21, wq22, P2, P3, P4);             // q2a -> P3, q2b -> P4
    __syncthreads();

    // logits[h][t] = sum_i c[h][i] * q2h[i][t]  (in-order)
    if (tid < 2 * SS) {
        int h = tid >= SS, t = tid - (h ? SS : 0);
        const float* q2 = h ? P4 : P3;
        const float* ch = sc + (h << 7);
        float acc = 0.f;
        #pragma unroll 8
        for (int i = 0; i < HH; i++)
            acc = fmaf(ch[i], q2[i * SP + t], acc);
        sw[h * 72 + t] = acc;
    }
    __syncthreads();
    if (tid < 64) {                               // softmax rows (warps 0,1)
        int h = tid >> 5, lane = tid & 31;
        softmax_row(sw + h * 72, lane);
    }
    __syncthreads();
    if (tid < 2 * HH) {                           // yw[h][j] = sum_t w[h][t] * Y2[j][t]
        int h = tid >> 7, j = tid & 127;
        const float* wrow = sw + h * 72;
        float acc = 0.f;
        #pragma unroll
        for (int t = 0; t < SP; t += 4) {
            float4 y4 = *(const float4*)(P2 + j * SP + t);
            float4 w4 = *(const float4*)(wrow + t);
            acc = dot4(y4, w4, acc);
        }
        syw[(h << 7) + j] = acc;
    }
    __syncthreads();
    if (tid < 2 * HH) {                           // att[h][i] = sum_j Wv2h[i][j] * yw[h][j]
        int h = tid >> 7, i = tid & 127;
        const float* Wv = h ? wv22 : wv21;
        const float* yh = syw + (h << 7);
        float acc = 0.f;
        #pragma unroll 8
        for (int j = 0; j < HH; j += 4) {
            float4 w4 = *(const float4*)(Wv + i * HH + j);
            float4 y4 = *(const float4*)(yh + j);
            acc = dot4(w4, y4, acc);
        }
        satt[(h << 7) + i] = acc;
    }
    __syncthreads();

    // head: h2 = tanh(cat(att) @ L2), h3 = tanh(h2 @ L3), score = h3 @ L4
    if (tid < HH) {
        float acc = 0.f;
        #pragma unroll 8
        for (int i = 0; i < 2 * HH; i++)
            acc = fmaf(satt[i], L2[i * HH + tid], acc);
        sh2[tid] = tanhf(acc);
    }
    __syncthreads();
    if (tid < 64) {
        float acc = 0.f;
        #pragma unroll 8
        for (int j = 0; j < HH; j++)
            acc = fmaf(sh2[j], L3[j * 64 + tid], acc);
        sh3[tid] = tanhf(acc);
    }
    __syncthreads();
    if (tid == 0) {
        float acc = 0.f;
        #pragma unroll
        for (int m = 0; m < 64; m++) acc = fmaf(sh3[m], L4[m], acc);
        out[b] = acc;
    }
}

extern "C" void kernel_launch(void* const* d_in, const int* in_sizes, int n_in,
                              void* d_out, int out_size) {
    const float* inputs = (const float*)d_in[0];
    const float* emb    = (const float*)d_in[1];
    const float* wk11   = (const float*)d_in[2];
    const float* wq11   = (const float*)d_in[3];
    const float* wv11   = (const float*)d_in[4];
    const float* wk12   = (const float*)d_in[5];
    const float* wq12   = (const float*)d_in[6];
    const float* wv12   = (const float*)d_in[7];
    const float* L1     = (const float*)d_in[8];
    const float* wk21   = (const float*)d_in[9];
    const float* wq21   = (const float*)d_in[10];
    const float* wv21   = (const float*)d_in[11];
    const float* wk22   = (const float*)d_in[12];
    const float* wq22   = (const float*)d_in[13];
    const float* wv22   = (const float*)d_in[14];
    const float* L2     = (const float*)d_in[15];
    const float* L3     = (const float*)d_in[16];
    const float* L4     = (const float*)d_in[17];
    (void)n_in; (void)in_sizes;

    int B = out_size;  // one score per board (8192)

    size_t smem = SMEM_FLOATS * sizeof(float);
    cudaFuncSetAttribute(board_kernel, cudaFuncAttributeMaxDynamicSharedMemorySize, (int)smem);

    board_kernel<<<B, NT, smem>>>(inputs, emb,
                                  wk11, wq11, wv11, wk12, wq12, wv12, L1,
                                  wk21, wq21, wv21, wk22, wq22, wv22, L2, L3, L4,
                                  (float*)d_out);
}